// round 9
// baseline (speedup 1.0000x reference)
#include <cuda_runtime.h>
#include <cuda_fp16.h>
#include <math.h>
#include <stdint.h>

// Problem shapes
#define Bn  256
#define Kn  64
#define Dn  1024
#define Hn  4
#define NLn 3

// Output layout in d_out (fp32): logits (B*NL), alpha (B*H*K), head_weights (B*H)
#define ALPHA_OFF 768
#define HW_OFF    (768 + Bn*Hn*Kn)

// HMMA GEMM tiling: CTA 128x128, warp tile 32x64, 8 warps, 2 CTAs/SM
#define TCM 128
#define TCN 128
#define KC  64                  // K elems per chunk (64 fp16 = 128B row)
#define NCHUNK (Dn / KC)        // 16
#define NET    (Dn / TCN)       // 8 e-tiles
#define NTHREADS 256
#define NSTAGE 3

typedef unsigned long long u64;

// -------- scratch (static device globals; no allocation allowed) --------
__device__ float g_wcsum[Hn * Dn];
__device__ float g_upart[NET * Bn * Hn * Kn];   // 2 MB
__device__ float g_eah[Bn * Hn * Dn];
__device__ float g_feat[Bn * 4 * Dn];
__device__ float g_hidpart[4 * Bn * Dn];
// fp16 operands (single-rounded)
__device__ __half g_Ef[Bn * Kn * Dn];    // 32 MB
__device__ __half g_Wt[Hn * Dn * Dn];    // 8 MB  (transposed: [h][e][d])

// -------- helpers --------
__device__ __forceinline__ uint32_t smem_u32(const void* p) {
    uint32_t a;
    asm("{ .reg .u64 t; cvta.to.shared.u64 t, %1; cvt.u32.u64 %0, t; }" : "=r"(a) : "l"(p));
    return a;
}
__device__ __forceinline__ float tanhfast(float x) {
    float y; asm("tanh.approx.f32 %0, %1;" : "=f"(y) : "f"(x)); return y;
}
#define SWZ128(o) ((o) ^ (((o) >> 3) & 0x70))

__device__ __forceinline__ void cp16(uint32_t saddr, const void* gptr) {
    asm volatile("cp.async.cg.shared.global [%0], [%1], 16;"
                 :: "r"(saddr), "l"(__cvta_generic_to_global(gptr)) : "memory");
}
#define CP_COMMIT() asm volatile("cp.async.commit_group;" ::: "memory")
#define CP_WAIT(n)  asm volatile("cp.async.wait_group %0;" :: "n"(n) : "memory")

#define LDSM_X4(r0, r1, r2, r3, addr) \
    asm volatile("ldmatrix.sync.aligned.m8n8.x4.shared.b16 {%0,%1,%2,%3}, [%4];" \
                 : "=r"(r0), "=r"(r1), "=r"(r2), "=r"(r3) : "r"(addr))

// fp16-accumulate MMA: d,c are 2 x b32 (4 halves)
#define MMA_F16ACC(d0, d1, a, b0, b1) \
    asm volatile("mma.sync.aligned.m16n8k16.row.col.f16.f16.f16.f16 " \
                 "{%0,%1}, {%2,%3,%4,%5}, {%6,%7}, {%0,%1};" \
                 : "+r"(d0), "+r"(d1) \
                 : "r"((a)[0]), "r"((a)[1]), "r"((a)[2]), "r"((a)[3]), \
                   "r"(b0), "r"(b1))

// smem stage layout: A(16KB) + B(16KB) = 32KB per stage
#define OFF_A   0
#define OFF_B   16384
#define STAGE_BYTES 32768
#define SM_EXTRA (NSTAGE * STAGE_BYTES)               // epilogue arrays beyond stages
#define SMEM_TOTAL (NSTAGE * STAGE_BYTES + 4096)      // 102400 -> 2 CTAs/SM

// -------- K0a: convert e_emb to fp16 --------
__global__ void k_cvtE(const float* __restrict__ e) {
    size_t i = (size_t)blockIdx.x * 256 + threadIdx.x;   // over float4s
    float4 x = ((const float4*)e)[i];
    __half h0 = __float2half_rn(x.x), h1 = __float2half_rn(x.y);
    __half h2 = __float2half_rn(x.z), h3 = __float2half_rn(x.w);
    ((__half2*)g_Ef)[2*i    ] = __halves2half2(h0, h1);
    ((__half2*)g_Ef)[2*i + 1] = __halves2half2(h2, h3);
}

// -------- K0b: transpose W_e[h][d][e] -> Wt[h][e][d] fp16 --------
__global__ void k_cvtW(const float* __restrict__ W) {
    __shared__ float t[32][33];
    const int h  = blockIdx.z;
    const int dB = blockIdx.y * 32;
    const int eB = blockIdx.x * 32;
    const int lx = threadIdx.x & 31, ly = threadIdx.x >> 5;  // 32 x 8
    #pragma unroll
    for (int r = 0; r < 4; ++r)
        t[ly + 8*r][lx] = W[((size_t)h*Dn + dB + ly + 8*r) * Dn + eB + lx];
    __syncthreads();
    #pragma unroll
    for (int r = 0; r < 4; ++r) {
        float x = t[lx][ly + 8*r];
        size_t oi = ((size_t)h*Dn + eB + ly + 8*r) * Dn + dB + lx;
        g_Wt[oi] = __float2half_rn(x);
    }
}

// -------- K1: Wc_sum[h,d] = sum_e W_c[h,d,e] --------
__global__ void k_wcsum(const float* __restrict__ W_c) {
    int warp = (blockIdx.x * blockDim.x + threadIdx.x) >> 5;
    int lane = threadIdx.x & 31;
    if (warp >= Hn * Dn) return;
    const float* p = W_c + (size_t)warp * Dn;
    float s = 0.f;
    #pragma unroll 8
    for (int j = lane; j < Dn; j += 32) s += p[j];
    #pragma unroll
    for (int o = 16; o; o >>= 1) s += __shfl_down_sync(0xffffffffu, s, o);
    if (!lane) g_wcsum[warp] = s;
}

// -------- K2: HMMA fused  P = E @ Wt^T (fp16, fp16-acc per chunk);
//              u = sum_e tanh(cp+P)*v ----
// 8 warps, warp tile 32x64; 2 CTAs/SM; fold f16 chunk-acc to f32 each chunk
__global__ void __launch_bounds__(NTHREADS, 2)
k_attn_mma(const float* __restrict__ c_out, const float* __restrict__ v)
{
    extern __shared__ char smem[];
    const uint32_t sb = smem_u32(smem);
    const int tid   = threadIdx.x;
    const int wid   = tid >> 5;
    const int lane  = tid & 31;
    const int warpM = wid >> 1;     // 0..3 (32 rows each)
    const int warpN = wid & 1;      // 0..1 (64 cols each)

    const int et      = blockIdx.x;          // 0..7
    const int rowBase = blockIdx.y * TCM;    // global GEMM row base
    const int h       = blockIdx.z;          // 0..3
    const int eBase   = et * TCN;

    const __half* Ap = g_Ef + (size_t)rowBase * Dn;
    const __half* Bp = g_Wt + ((size_t)h * Dn + eBase) * Dn;

    // epilogue smem region (beyond the stages)
    float* s_cce0 = (float*)(smem + SM_EXTRA);       // 128
    float* s_cce1 = s_cce0 + TCN;                    // 128
    float* s_vv   = s_cce1 + TCN;                    // 128
    float* s_red  = s_vv + TCN;                      // [128][2]

    const int b0 = rowBase >> 6;
    {   // precompute per-column scalars (overlaps with first loads)
        int e0 = eBase + (tid & 127);
        float wc0 = g_wcsum[h * Dn + e0];
        if (tid < 128) {
            s_cce0[tid] = c_out[b0 * Dn + e0] * wc0;
            s_vv[tid]   = v[h * Dn + e0];
        } else {
            s_cce1[tid - 128] = c_out[(b0 + 1) * Dn + e0] * wc0;
        }
    }

    // per-thread load mapping: A = 1024 16B segs, B = 1024 segs
    int arow[4], ac16[4]; uint32_t aso[4];
    #pragma unroll
    for (int i = 0; i < 4; ++i) {
        int seg = tid + i * NTHREADS;
        arow[i] = seg >> 3; ac16[i] = seg & 7;
        aso[i] = SWZ128((uint32_t)(arow[i] * 128 + ac16[i] * 16));
    }

    float acc[2][8][4];
    #pragma unroll
    for (int mt = 0; mt < 2; ++mt)
        #pragma unroll
        for (int nt = 0; nt < 8; ++nt)
            #pragma unroll
            for (int j = 0; j < 4; ++j) acc[mt][nt][j] = 0.f;

    // ldmatrix base offsets
    const uint32_t aRowB = (uint32_t)((warpM * 32 + (lane & 15)) * 128);
    const uint32_t bRowB = (uint32_t)((warpN * 64 + (lane & 15)) * 128);
    const uint32_t colSel = (uint32_t)((lane >> 4) * 16);

    // prologue: issue chunks 0 and 1 (one commit group each)
    #pragma unroll
    for (int pc = 0; pc < 2; ++pc) {
        const uint32_t st = sb + pc * STAGE_BYTES;
        const int dB = pc * KC;
        #pragma unroll
        for (int i = 0; i < 4; ++i) {
            cp16(st + OFF_A + aso[i], Ap + (size_t)arow[i] * Dn + dB + ac16[i] * 8);
            cp16(st + OFF_B + aso[i], Bp + (size_t)arow[i] * Dn + dB + ac16[i] * 8);
        }
        CP_COMMIT();
    }

    int stage = 0;
    for (int c = 0; c < NCHUNK; ++c) {
        if (c + 2 < NCHUNK) { CP_WAIT(1); } else { CP_WAIT(0); }
        __syncthreads();

        const uint32_t st = sb + stage * STAGE_BYTES;

        // fp16 chunk accumulators (zeroed each chunk)
        uint32_t a16[2][8][2];
        #pragma unroll
        for (int mt = 0; mt < 2; ++mt)
            #pragma unroll
            for (int nt = 0; nt < 8; ++nt) { a16[mt][nt][0] = 0u; a16[mt][nt][1] = 0u; }

        #pragma unroll
        for (int ks = 0; ks < KC / 16; ++ks) {
            const uint32_t kcol = ks * 32 + colSel;
            uint32_t af[2][4];
            #pragma unroll
            for (int mt = 0; mt < 2; ++mt) {
                uint32_t off = SWZ128(aRowB + (uint32_t)(mt * 16 * 128) + kcol);
                LDSM_X4(af[mt][0], af[mt][1], af[mt][2], af[mt][3], st + OFF_A + off);
            }
            #pragma unroll
            for (int p = 0; p < 4; ++p) {
                uint32_t off = SWZ128(bRowB + (uint32_t)(p * 16 * 128) + kcol);
                uint32_t r0, r1, r2, r3;
                LDSM_X4(r0, r1, r2, r3, st + OFF_B + off);
                MMA_F16ACC(a16[0][2*p  ][0], a16[0][2*p  ][1], af[0], r0, r2);
                MMA_F16ACC(a16[0][2*p+1][0], a16[0][2*p+1][1], af[0], r1, r3);
                MMA_F16ACC(a16[1][2*p  ][0], a16[1][2*p  ][1], af[1], r0, r2);
                MMA_F16ACC(a16[1][2*p+1][0], a16[1][2*p+1][1], af[1], r1, r3);
            }
        }

        // fold fp16 chunk partials into fp32 master accumulator
        #pragma unroll
        for (int mt = 0; mt < 2; ++mt)
            #pragma unroll
            for (int nt = 0; nt < 8; ++nt) {
                float2 f01 = __half22float2(*(__half2*)&a16[mt][nt][0]);
                float2 f23 = __half22float2(*(__half2*)&a16[mt][nt][1]);
                acc[mt][nt][0] += f01.x;
                acc[mt][nt][1] += f01.y;
                acc[mt][nt][2] += f23.x;
                acc[mt][nt][3] += f23.y;
            }

        // issue chunk c+2 into the stage all warps finished reading last iter
        if (c + 2 < NCHUNK) {
            int ns = stage + 2; if (ns >= NSTAGE) ns -= NSTAGE;
            const uint32_t stn = sb + ns * STAGE_BYTES;
            const int dB = (c + 2) * KC;
            #pragma unroll
            for (int i = 0; i < 4; ++i) {
                cp16(stn + OFF_A + aso[i], Ap + (size_t)arow[i] * Dn + dB + ac16[i] * 8);
                cp16(stn + OFF_B + aso[i], Bp + (size_t)arow[i] * Dn + dB + ac16[i] * 8);
            }
            CP_COMMIT();
        }
        if (++stage == NSTAGE) stage = 0;
    }

    // ---- epilogue: tanh(P + cce) * v, reduce over this CTA's 128 e-cols ----
    const int gRow = lane >> 2;
    const int c2   = (lane & 3) * 2;
    const float* cce = (warpM >= 2) ? s_cce1 : s_cce0;

    #pragma unroll
    for (int mt = 0; mt < 2; ++mt) {
        #pragma unroll
        for (int h2 = 0; h2 < 2; ++h2) {
            float p = 0.f;
            #pragma unroll
            for (int nt = 0; nt < 8; ++nt) {
                int e0 = warpN * 64 + nt * 8 + c2;
                float v0 = acc[mt][nt][h2 * 2 + 0];
                float v1 = acc[mt][nt][h2 * 2 + 1];
                p += tanhfast(v0 + cce[e0    ]) * s_vv[e0    ];
                p += tanhfast(v1 + cce[e0 + 1]) * s_vv[e0 + 1];
            }
            p += __shfl_xor_sync(0xffffffffu, p, 1);
            p += __shfl_xor_sync(0xffffffffu, p, 2);
            if ((lane & 3) == 0) {
                int lrow2 = warpM * 32 + mt * 16 + h2 * 8 + gRow;
                s_red[lrow2 * 2 + warpN] = p;
            }
        }
    }
    __syncthreads();

    if (tid < 128) {
        float s = s_red[tid*2] + s_red[tid*2+1];
        int rg = rowBase + tid;
        int bb = rg >> 6, kk = rg & 63;
        g_upart[et * (Bn * Hn * Kn) + ((bb * Hn + h) << 6) + kk] = s;
    }
}

// -------- K3: sum u partials, mask, softmax over K=64 --------
__global__ void k_softmax(const int* __restrict__ mask, float* __restrict__ out) {
    const int row = blockIdx.x;
    const int k   = threadIdx.x;
    const int b   = row >> 2;
    float s = 0.f;
    #pragma unroll
    for (int nt = 0; nt < NET; ++nt) s += g_upart[nt * (Bn*Hn*Kn) + row * Kn + k];
    if (mask[b * Kn + k] == 0) s = -__int_as_float(0x7f800000);

    __shared__ float sm[64];
    sm[k] = s; __syncthreads();
    #pragma unroll
    for (int o = 32; o; o >>= 1) { if (k < o) sm[k] = fmaxf(sm[k], sm[k+o]); __syncthreads(); }
    float mx = sm[0]; __syncthreads();
    float ex = __expf(s - mx);
    sm[k] = ex; __syncthreads();
    #pragma unroll
    for (int o = 32; o; o >>= 1) { if (k < o) sm[k] += sm[k+o]; __syncthreads(); }
    out[ALPHA_OFF + row * Kn + k] = ex / sm[0];
}

// -------- K4: e_att_heads = alpha @ e_emb  (grid: (D/256) x B) --------
__global__ void k_eah(const float* __restrict__ e_emb, const float* __restrict__ out) {
    const int b = blockIdx.y, tid = threadIdx.x;
    const int d = blockIdx.x * 256 + tid;
    __shared__ float sal[Hn * Kn];
    sal[tid] = out[ALPHA_OFF + b * (Hn*Kn) + tid];
    __syncthreads();
    float a0 = 0.f, a1 = 0.f, a2 = 0.f, a3 = 0.f;
    const float* ep = e_emb + (size_t)b * Kn * Dn + d;
    #pragma unroll 8
    for (int k = 0; k < Kn; ++k) {
        float ev = ep[k * Dn];
        a0 = fmaf(sal[k      ], ev, a0);
        a1 = fmaf(sal[64  + k], ev, a1);
        a2 = fmaf(sal[128 + k], ev, a2);
        a3 = fmaf(sal[192 + k], ev, a3);
    }
    g_eah[(b*Hn + 0) * Dn + d] = a0;
    g_eah[(b*Hn + 1) * Dn + d] = a1;
    g_eah[(b*Hn + 2) * Dn + d] = a2;
    g_eah[(b*Hn + 3) * Dn + d] = a3;
}

// -------- K5: gate logits + softmax over H + feature vector (fused) --------
__global__ void k_gate(const float* __restrict__ c_out, const float* __restrict__ gate_w,
                       const float* __restrict__ gate_b, float* __restrict__ out) {
    const int b = blockIdx.x, tid = threadIdx.x;
    float pv[5] = {0.f, 0.f, 0.f, 0.f, 0.f};
    for (int d = tid; d < Dn; d += 256) {
        float gwc = gate_w[d], gwe = gate_w[Dn + d];
        pv[0] = fmaf(c_out[b*Dn + d], gwc, pv[0]);
        pv[1] = fmaf(g_eah[(b*Hn + 0)*Dn + d], gwe, pv[1]);
        pv[2] = fmaf(g_eah[(b*Hn + 1)*Dn + d], gwe, pv[2]);
        pv[3] = fmaf(g_eah[(b*Hn + 2)*Dn + d], gwe, pv[3]);
        pv[4] = fmaf(g_eah[(b*Hn + 3)*Dn + d], gwe, pv[4]);
    }
    __shared__ float red[256];
    __shared__ float vals[5];
    __shared__ float shw[4];
    for (int i = 0; i < 5; ++i) {
        red[tid] = pv[i]; __syncthreads();
        #pragma unroll
        for (int o = 128; o; o >>= 1) { if (tid < o) red[tid] += red[tid+o]; __syncthreads(); }
        if (!tid) vals[i] = red[0];
        __syncthreads();
    }
    if (!tid) {
        float gb = gate_b[0];
        float g0 = vals[0] + vals[1] + gb, g1 = vals[0] + vals[2] + gb;
        float g2 = vals[0] + vals[3] + gb, g3 = vals[0] + vals[4] + gb;
        float mx = fmaxf(fmaxf(g0, g1), fmaxf(g2, g3));
        float e0 = __expf(g0 - mx), e1 = __expf(g1 - mx);
        float e2 = __expf(g2 - mx), e3 = __expf(g3 - mx);
        float inv = 1.f / (e0 + e1 + e2 + e3);
        shw[0] = e0*inv; shw[1] = e1*inv; shw[2] = e2*inv; shw[3] = e3*inv;
        out[HW_OFF + b*Hn + 0] = shw[0]; out[HW_OFF + b*Hn + 1] = shw[1];
        out[HW_OFF + b*Hn + 2] = shw[2]; out[HW_OFF + b*Hn + 3] = shw[3];
    }
    __syncthreads();
    float hw0 = shw[0], hw1 = shw[1], hw2 = shw[2], hw3 = shw[3];
    #pragma unroll
    for (int q = 0; q < 4; ++q) {
        int d = q * 256 + tid;
        float ea = hw0 * g_eah[(b*Hn+0)*Dn + d] + hw1 * g_eah[(b*Hn+1)*Dn + d]
                 + hw2 * g_eah[(b*Hn+2)*Dn + d] + hw3 * g_eah[(b*Hn+3)*Dn + d];
        float c = c_out[b*Dn + d];
        const int base = b * 4 * Dn;
        g_feat[base +        d] = c;
        g_feat[base +   Dn + d] = ea;
        g_feat[base + 2*Dn + d] = fabsf(c - ea);
        g_feat[base + 3*Dn + d] = c * ea;
    }
}

// -------- K7: hid_pre = feat @ w1.T  (split-k=4, deterministic) --------
#define M2 64
#define N2 64
#define K2 16
__global__ void __launch_bounds__(256)
k_mlp1(const float* __restrict__ w1) {
    __shared__ float A2[K2][M2];
    __shared__ float B2[K2][N2];
    const int tid = threadIdx.x;
    const int oBase = blockIdx.x * N2;
    const int rBase = blockIdx.y * M2;
    const int kBase = blockIdx.z * 1024;
    const int ty = tid >> 4, tx = tid & 15;
    const int lr = tid >> 2;
    const int lk = (tid & 3) * 4;

    const float* Ag = g_feat + (rBase + lr) * (4*Dn) + kBase + lk;
    const float* Bg = w1     + (oBase + lr) * (4*Dn) + kBase + lk;

    float acc[4][4];
    #pragma unroll
    for (int i = 0; i < 4; ++i)
        #pragma unroll
        for (int j = 0; j < 4; ++j) acc[i][j] = 0.f;

    for (int kt = 0; kt < 1024; kt += K2) {
        float4 a4 = *(const float4*)(Ag + kt);
        float4 b4 = *(const float4*)(Bg + kt);
        __syncthreads();
        A2[lk+0][lr] = a4.x; A2[lk+1][lr] = a4.y; A2[lk+2][lr] = a4.z; A2[lk+3][lr] = a4.w;
        B2[lk+0][lr] = b4.x; B2[lk+1][lr] = b4.y; B2[lk+2][lr] = b4.z; B2[lk+3][lr] = b4.w;
        __syncthreads();
        #pragma unroll
        for (int kk = 0; kk < K2; ++kk) {
            float4 av = *(const float4*)&A2[kk][ty*4];
            float4 bv = *(const float4*)&B2[kk][tx*4];
            float a_[4] = {av.x, av.y, av.z, av.w};
            float b_[4] = {bv.x, bv.y, bv.z, bv.w};
            #pragma unroll
            for (int i = 0; i < 4; ++i)
                #pragma unroll
                for (int j = 0; j < 4; ++j)
                    acc[i][j] = fmaf(a_[i], b_[j], acc[i][j]);
        }
    }
    #pragma unroll
    for (int i = 0; i < 4; ++i)
        #pragma unroll
        for (int j = 0; j < 4; ++j)
            g_hidpart[blockIdx.z * (Bn*Dn) + (rBase + ty*4 + i) * Dn + oBase + tx*4 + j] = acc[i][j];
}

// -------- K8: relu(hid_pre + b1) @ w2.T + b2 -> logits --------
__global__ void k_logits(const float* __restrict__ b1, const float* __restrict__ w2,
                         const float* __restrict__ b2, float* __restrict__ out) {
    const int b = blockIdx.x, tid = threadIdx.x;
    float a0 = 0.f, a1 = 0.f, a2 = 0.f;
    for (int d = tid; d < Dn; d += 128) {
        float hp = g_hidpart[            b*Dn + d] + g_hidpart[  Bn*Dn + b*Dn + d]
                 + g_hidpart[2*Bn*Dn +   b*Dn + d] + g_hidpart[3*Bn*Dn + b*Dn + d]
                 + b1[d];
        hp = fmaxf(hp, 0.f);
        a0 = fmaf(hp, w2[        d], a0);
        a1 = fmaf(hp, w2[  Dn + d], a1);
        a2 = fmaf(hp, w2[2*Dn + d], a2);
    }
    __shared__ float red[128];
    __shared__ float vals[3];
    float pv[3] = {a0, a1, a2};
    for (int i = 0; i < 3; ++i) {
        red[tid] = pv[i]; __syncthreads();
        #pragma unroll
        for (int o = 64; o; o >>= 1) { if (tid < o) red[tid] += red[tid+o]; __syncthreads(); }
        if (!tid) vals[i] = red[0];
        __syncthreads();
    }
    if (!tid) {
        out[b*NLn + 0] = vals[0] + b2[0];
        out[b*NLn + 1] = vals[1] + b2[1];
        out[b*NLn + 2] = vals[2] + b2[2];
    }
}

extern "C" void kernel_launch(void* const* d_in, const int* in_sizes, int n_in,
                              void* d_out, int out_size) {
    const float* c_out  = (const float*)d_in[0];
    const float* e_emb  = (const float*)d_in[1];
    const int*   emask  = (const int*)  d_in[2];
    const float* W_c    = (const float*)d_in[3];
    const float* W_e    = (const float*)d_in[4];
    const float* v      = (const float*)d_in[5];
    const float* gate_w = (const float*)d_in[6];
    const float* gate_b = (const float*)d_in[7];
    const float* w1     = (const float*)d_in[8];
    const float* b1     = (const float*)d_in[9];
    const float* w2     = (const float*)d_in[10];
    const float* b2     = (const float*)d_in[11];
    float* out = (float*)d_out;

    cudaFuncSetAttribute(k_attn_mma, cudaFuncAttributeMaxDynamicSharedMemorySize, SMEM_TOTAL);

    k_cvtE<<<(Bn*Kn*Dn/4 + 255)/256, 256>>>(e_emb);
    k_cvtW<<<dim3(Dn/32, Dn/32, Hn), 256>>>(W_e);
    k_wcsum<<<(Hn*Dn*32 + 255)/256, 256>>>(W_c);
    k_attn_mma<<<dim3(NET, (Bn*Kn)/TCM, Hn), NTHREADS, SMEM_TOTAL>>>(c_out, v);
    k_softmax<<<Bn*Hn, Kn>>>(emask, out);
    k_eah<<<dim3(Dn/256, Bn), 256>>>(e_emb, out);
    k_gate<<<Bn, 256>>>(c_out, gate_w, gate_b, out);
    k_mlp1<<<dim3(Dn/N2, Bn/M2, 4), 256>>>(w1);
    k_logits<<<Bn, 128>>>(b1, w2, b2, out);
}

// round 10
// speedup vs baseline: 1.1778x; 1.1778x over previous
#include <cuda_runtime.h>
#include <cuda_fp16.h>
#include <math.h>
#include <stdint.h>

// Problem shapes
#define Bn  256
#define Kn  64
#define Dn  1024
#define Hn  4
#define NLn 3

// Output layout in d_out (fp32): logits (B*NL), alpha (B*H*K), head_weights (B*H)
#define ALPHA_OFF 768
#define HW_OFF    (768 + Bn*Hn*Kn)

// HMMA GEMM tiling: CTA 128x128, warp tile 32x64, 8 warps, 2 CTAs/SM
#define TCM 128
#define TCN 128
#define KC  64                  // K elems per chunk (64 fp16 = 128B row)
#define NCHUNK (Dn / KC)        // 16
#define NET    (Dn / TCN)       // 8 e-tiles
#define NTHREADS 256
#define NSTAGE 3

typedef unsigned long long u64;

// -------- scratch (static device globals; no allocation allowed) --------
__device__ float g_wcsum[Hn * Dn];
__device__ float g_upart[NET * Bn * Hn * Kn];   // 2 MB
__device__ float g_eah[Bn * Hn * Dn];
__device__ float g_feat[Bn * 4 * Dn];
__device__ float g_hidpart[4 * Bn * Dn];
// fp16 operands (single-rounded)
__device__ __half g_Ef[Bn * Kn * Dn];    // 32 MB
__device__ __half g_Wt[Hn * Dn * Dn];    // 8 MB  (transposed: [h][e][d])

// -------- helpers --------
__device__ __forceinline__ uint32_t smem_u32(const void* p) {
    uint32_t a;
    asm("{ .reg .u64 t; cvta.to.shared.u64 t, %1; cvt.u32.u64 %0, t; }" : "=r"(a) : "l"(p));
    return a;
}
__device__ __forceinline__ float tanhfast(float x) {
    float y; asm("tanh.approx.f32 %0, %1;" : "=f"(y) : "f"(x)); return y;
}
#define SWZ128(o) ((o) ^ (((o) >> 3) & 0x70))

__device__ __forceinline__ void cp16(uint32_t saddr, const void* gptr) {
    asm volatile("cp.async.cg.shared.global [%0], [%1], 16;"
                 :: "r"(saddr), "l"(__cvta_generic_to_global(gptr)) : "memory");
}
#define CP_COMMIT() asm volatile("cp.async.commit_group;" ::: "memory")
#define CP_WAIT(n)  asm volatile("cp.async.wait_group %0;" :: "n"(n) : "memory")

#define LDSM_X4(r0, r1, r2, r3, addr) \
    asm volatile("ldmatrix.sync.aligned.m8n8.x4.shared.b16 {%0,%1,%2,%3}, [%4];" \
                 : "=r"(r0), "=r"(r1), "=r"(r2), "=r"(r3) : "r"(addr))

#define MMA_F16(c, a, b) \
    asm volatile("mma.sync.aligned.m16n8k16.row.col.f32.f16.f16.f32 " \
                 "{%0,%1,%2,%3}, {%4,%5,%6,%7}, {%8,%9}, {%0,%1,%2,%3};" \
                 : "+f"((c)[0]), "+f"((c)[1]), "+f"((c)[2]), "+f"((c)[3]) \
                 : "r"((a)[0]), "r"((a)[1]), "r"((a)[2]), "r"((a)[3]), \
                   "r"((b)[0]), "r"((b)[1]))

// smem stage layout: A(16KB) + B(16KB) = 32KB per stage
#define OFF_A   0
#define OFF_B   16384
#define STAGE_BYTES 32768
#define SM_EXTRA (NSTAGE * STAGE_BYTES)               // epilogue arrays beyond stages
#define SMEM_TOTAL (NSTAGE * STAGE_BYTES + 4096)      // 102400 -> 2 CTAs/SM

// -------- K0: fused preprocessing (cvtE | cvtW | wcsum via grid demux) ----
#define NBLK_E (Bn*Kn*Dn/4/256)      // 16384
#define NBLK_W ((Dn/32)*(Dn/32)*Hn)  // 4096
#define NBLK_S (Hn*Dn*32/256)        // 512
__global__ void k_prep(const float* __restrict__ e, const float* __restrict__ W,
                       const float* __restrict__ W_c) {
    __shared__ float t[32][33];
    const int bx = blockIdx.x;
    const int tid = threadIdx.x;
    if (bx < NBLK_E) {
        // convert e_emb to fp16
        size_t i = (size_t)bx * 256 + tid;   // over float4s
        float4 x = ((const float4*)e)[i];
        __half h0 = __float2half_rn(x.x), h1 = __float2half_rn(x.y);
        __half h2 = __float2half_rn(x.z), h3 = __float2half_rn(x.w);
        ((__half2*)g_Ef)[2*i    ] = __halves2half2(h0, h1);
        ((__half2*)g_Ef)[2*i + 1] = __halves2half2(h2, h3);
    } else if (bx < NBLK_E + NBLK_W) {
        // transpose W_e[h][d][e] -> Wt[h][e][d] fp16
        const int b  = bx - NBLK_E;
        const int h  = b >> 10;              // / (32*32)
        const int dB = ((b & 1023) >> 5) * 32;
        const int eB = (b & 31) * 32;
        const int lx = tid & 31, ly = tid >> 5;  // 32 x 8
        #pragma unroll
        for (int r = 0; r < 4; ++r)
            t[ly + 8*r][lx] = W[((size_t)h*Dn + dB + ly + 8*r) * Dn + eB + lx];
        __syncthreads();
        #pragma unroll
        for (int r = 0; r < 4; ++r) {
            float x = t[lx][ly + 8*r];
            size_t oi = ((size_t)h*Dn + eB + ly + 8*r) * Dn + dB + lx;
            g_Wt[oi] = __float2half_rn(x);
        }
    } else {
        // Wc_sum[h,d] = sum_e W_c[h,d,e]
        int warp = (((bx - NBLK_E - NBLK_W) << 8) + tid) >> 5;
        int lane = tid & 31;
        const float* p = W_c + (size_t)warp * Dn;
        float s = 0.f;
        #pragma unroll 8
        for (int j = lane; j < Dn; j += 32) s += p[j];
        #pragma unroll
        for (int o = 16; o; o >>= 1) s += __shfl_down_sync(0xffffffffu, s, o);
        if (!lane) g_wcsum[warp] = s;
    }
}

// -------- K2: HMMA fused  P = E @ Wt^T (fp16);  u = sum_e tanh(cp+P)*v ----
// 8 warps, warp tile 32x64; 2 CTAs/SM; prefetch issued BEFORE mma loop
__global__ void __launch_bounds__(NTHREADS, 2)
k_attn_mma(const float* __restrict__ c_out, const float* __restrict__ v)
{
    extern __shared__ char smem[];
    const uint32_t sb = smem_u32(smem);
    const int tid   = threadIdx.x;
    const int wid   = tid >> 5;
    const int lane  = tid & 31;
    const int warpM = wid >> 1;     // 0..3 (32 rows each)
    const int warpN = wid & 1;      // 0..1 (64 cols each)

    const int et      = blockIdx.x;          // 0..7
    const int rowBase = blockIdx.y * TCM;    // global GEMM row base
    const int h       = blockIdx.z;          // 0..3
    const int eBase   = et * TCN;

    const __half* Ap = g_Ef + (size_t)rowBase * Dn;
    const __half* Bp = g_Wt + ((size_t)h * Dn + eBase) * Dn;

    // epilogue smem region (beyond the stages)
    float* s_cce0 = (float*)(smem + SM_EXTRA);       // 128
    float* s_cce1 = s_cce0 + TCN;                    // 128
    float* s_vv   = s_cce1 + TCN;                    // 128
    float* s_red  = s_vv + TCN;                      // [128][2]

    const int b0 = rowBase >> 6;
    {   // precompute per-column scalars (overlaps with first loads)
        int e0 = eBase + (tid & 127);
        float wc0 = g_wcsum[h * Dn + e0];
        if (tid < 128) {
            s_cce0[tid] = c_out[b0 * Dn + e0] * wc0;
            s_vv[tid]   = v[h * Dn + e0];
        } else {
            s_cce1[tid - 128] = c_out[(b0 + 1) * Dn + e0] * wc0;
        }
    }

    // per-thread load mapping: A = 1024 16B segs, B = 1024 segs
    int arow[4], ac16[4]; uint32_t aso[4];
    #pragma unroll
    for (int i = 0; i < 4; ++i) {
        int seg = tid + i * NTHREADS;
        arow[i] = seg >> 3; ac16[i] = seg & 7;
        aso[i] = SWZ128((uint32_t)(arow[i] * 128 + ac16[i] * 16));
    }

    float acc[2][8][4];
    #pragma unroll
    for (int mt = 0; mt < 2; ++mt)
        #pragma unroll
        for (int nt = 0; nt < 8; ++nt)
            #pragma unroll
            for (int j = 0; j < 4; ++j) acc[mt][nt][j] = 0.f;

    // ldmatrix base offsets
    const uint32_t aRowB = (uint32_t)((warpM * 32 + (lane & 15)) * 128);
    const uint32_t bRowB = (uint32_t)((warpN * 64 + (lane & 15)) * 128);
    const uint32_t colSel = (uint32_t)((lane >> 4) * 16);

    // prologue: issue chunks 0 and 1 (one commit group each)
    #pragma unroll
    for (int pc = 0; pc < 2; ++pc) {
        const uint32_t st = sb + pc * STAGE_BYTES;
        const int dB = pc * KC;
        #pragma unroll
        for (int i = 0; i < 4; ++i) {
            cp16(st + OFF_A + aso[i], Ap + (size_t)arow[i] * Dn + dB + ac16[i] * 8);
            cp16(st + OFF_B + aso[i], Bp + (size_t)arow[i] * Dn + dB + ac16[i] * 8);
        }
        CP_COMMIT();
    }

    int stage = 0;
    for (int c = 0; c < NCHUNK; ++c) {
        if (c + 2 < NCHUNK) { CP_WAIT(1); } else { CP_WAIT(0); }
        __syncthreads();

        // EARLY prefetch of chunk c+2: slot (stage+2)%NSTAGE was fully consumed
        // at chunk c-1 (all warps synced since), so it is safe to overwrite now.
        // Issuing before the MMA loop hides the full L2 round-trip under compute.
        if (c + 2 < NCHUNK) {
            int ns = stage + 2; if (ns >= NSTAGE) ns -= NSTAGE;
            const uint32_t stn = sb + ns * STAGE_BYTES;
            const int dB = (c + 2) * KC;
            #pragma unroll
            for (int i = 0; i < 4; ++i) {
                cp16(stn + OFF_A + aso[i], Ap + (size_t)arow[i] * Dn + dB + ac16[i] * 8);
                cp16(stn + OFF_B + aso[i], Bp + (size_t)arow[i] * Dn + dB + ac16[i] * 8);
            }
            CP_COMMIT();
        }

        const uint32_t st = sb + stage * STAGE_BYTES;
        #pragma unroll
        for (int ks = 0; ks < KC / 16; ++ks) {
            const uint32_t kcol = ks * 32 + colSel;
            uint32_t af[2][4];
            #pragma unroll
            for (int mt = 0; mt < 2; ++mt) {
                uint32_t off = SWZ128(aRowB + (uint32_t)(mt * 16 * 128) + kcol);
                LDSM_X4(af[mt][0], af[mt][1], af[mt][2], af[mt][3], st + OFF_A + off);
            }
            uint32_t bf[8][2];
            #pragma unroll
            for (int p = 0; p < 4; ++p) {
                uint32_t off = SWZ128(bRowB + (uint32_t)(p * 16 * 128) + kcol);
                uint32_t r0, r1, r2, r3;
                LDSM_X4(r0, r1, r2, r3, st + OFF_B + off);
                bf[2*p][0] = r0; bf[2*p][1] = r2;
                bf[2*p+1][0] = r1; bf[2*p+1][1] = r3;
            }
            #pragma unroll
            for (int mt = 0; mt < 2; ++mt)
                #pragma unroll
                for (int nt = 0; nt < 8; ++nt)
                    MMA_F16(acc[mt][nt], af[mt], bf[nt]);
        }
        if (++stage == NSTAGE) stage = 0;
    }

    // ---- epilogue: tanh(P + cce) * v, reduce over this CTA's 128 e-cols ----
    const int gRow = lane >> 2;
    const int c2   = (lane & 3) * 2;
    const float* cce = (warpM >= 2) ? s_cce1 : s_cce0;

    #pragma unroll
    for (int mt = 0; mt < 2; ++mt) {
        #pragma unroll
        for (int h2 = 0; h2 < 2; ++h2) {
            float p = 0.f;
            #pragma unroll
            for (int nt = 0; nt < 8; ++nt) {
                int e0 = warpN * 64 + nt * 8 + c2;
                float v0 = acc[mt][nt][h2 * 2 + 0];
                float v1 = acc[mt][nt][h2 * 2 + 1];
                p += tanhfast(v0 + cce[e0    ]) * s_vv[e0    ];
                p += tanhfast(v1 + cce[e0 + 1]) * s_vv[e0 + 1];
            }
            p += __shfl_xor_sync(0xffffffffu, p, 1);
            p += __shfl_xor_sync(0xffffffffu, p, 2);
            if ((lane & 3) == 0) {
                int lrow2 = warpM * 32 + mt * 16 + h2 * 8 + gRow;
                s_red[lrow2 * 2 + warpN] = p;
            }
        }
    }
    __syncthreads();

    if (tid < 128) {
        float s = s_red[tid*2] + s_red[tid*2+1];
        int rg = rowBase + tid;
        int bb = rg >> 6, kk = rg & 63;
        g_upart[et * (Bn * Hn * Kn) + ((bb * Hn + h) << 6) + kk] = s;
    }
}

// -------- K3: sum u partials, mask, softmax over K=64 --------
__global__ void k_softmax(const int* __restrict__ mask, float* __restrict__ out) {
    const int row = blockIdx.x;
    const int k   = threadIdx.x;
    const int b   = row >> 2;
    float s = 0.f;
    #pragma unroll
    for (int nt = 0; nt < NET; ++nt) s += g_upart[nt * (Bn*Hn*Kn) + row * Kn + k];
    if (mask[b * Kn + k] == 0) s = -__int_as_float(0x7f800000);

    __shared__ float sm[64];
    sm[k] = s; __syncthreads();
    #pragma unroll
    for (int o = 32; o; o >>= 1) { if (k < o) sm[k] = fmaxf(sm[k], sm[k+o]); __syncthreads(); }
    float mx = sm[0]; __syncthreads();
    float ex = __expf(s - mx);
    sm[k] = ex; __syncthreads();
    #pragma unroll
    for (int o = 32; o; o >>= 1) { if (k < o) sm[k] += sm[k+o]; __syncthreads(); }
    out[ALPHA_OFF + row * Kn + k] = ex / sm[0];
}

// -------- K4: e_att_heads = alpha @ e_emb  (grid: (D/256) x B) --------
__global__ void k_eah(const float* __restrict__ e_emb, const float* __restrict__ out) {
    const int b = blockIdx.y, tid = threadIdx.x;
    const int d = blockIdx.x * 256 + tid;
    __shared__ float sal[Hn * Kn];
    sal[tid] = out[ALPHA_OFF + b * (Hn*Kn) + tid];
    __syncthreads();
    float a0 = 0.f, a1 = 0.f, a2 = 0.f, a3 = 0.f;
    const float* ep = e_emb + (size_t)b * Kn * Dn + d;
    #pragma unroll 8
    for (int k = 0; k < Kn; ++k) {
        float ev = ep[k * Dn];
        a0 = fmaf(sal[k      ], ev, a0);
        a1 = fmaf(sal[64  + k], ev, a1);
        a2 = fmaf(sal[128 + k], ev, a2);
        a3 = fmaf(sal[192 + k], ev, a3);
    }
    g_eah[(b*Hn + 0) * Dn + d] = a0;
    g_eah[(b*Hn + 1) * Dn + d] = a1;
    g_eah[(b*Hn + 2) * Dn + d] = a2;
    g_eah[(b*Hn + 3) * Dn + d] = a3;
}

// -------- K5: gate logits + softmax over H + feature vector (fused) --------
__global__ void k_gate(const float* __restrict__ c_out, const float* __restrict__ gate_w,
                       const float* __restrict__ gate_b, float* __restrict__ out) {
    const int b = blockIdx.x, tid = threadIdx.x;
    float pv[5] = {0.f, 0.f, 0.f, 0.f, 0.f};
    for (int d = tid; d < Dn; d += 256) {
        float gwc = gate_w[d], gwe = gate_w[Dn + d];
        pv[0] = fmaf(c_out[b*Dn + d], gwc, pv[0]);
        pv[1] = fmaf(g_eah[(b*Hn + 0)*Dn + d], gwe, pv[1]);
        pv[2] = fmaf(g_eah[(b*Hn + 1)*Dn + d], gwe, pv[2]);
        pv[3] = fmaf(g_eah[(b*Hn + 2)*Dn + d], gwe, pv[3]);
        pv[4] = fmaf(g_eah[(b*Hn + 3)*Dn + d], gwe, pv[4]);
    }
    __shared__ float red[256];
    __shared__ float vals[5];
    __shared__ float shw[4];
    for (int i = 0; i < 5; ++i) {
        red[tid] = pv[i]; __syncthreads();
        #pragma unroll
        for (int o = 128; o; o >>= 1) { if (tid < o) red[tid] += red[tid+o]; __syncthreads(); }
        if (!tid) vals[i] = red[0];
        __syncthreads();
    }
    if (!tid) {
        float gb = gate_b[0];
        float g0 = vals[0] + vals[1] + gb, g1 = vals[0] + vals[2] + gb;
        float g2 = vals[0] + vals[3] + gb, g3 = vals[0] + vals[4] + gb;
        float mx = fmaxf(fmaxf(g0, g1), fmaxf(g2, g3));
        float e0 = __expf(g0 - mx), e1 = __expf(g1 - mx);
        float e2 = __expf(g2 - mx), e3 = __expf(g3 - mx);
        float inv = 1.f / (e0 + e1 + e2 + e3);
        shw[0] = e0*inv; shw[1] = e1*inv; shw[2] = e2*inv; shw[3] = e3*inv;
        out[HW_OFF + b*Hn + 0] = shw[0]; out[HW_OFF + b*Hn + 1] = shw[1];
        out[HW_OFF + b*Hn + 2] = shw[2]; out[HW_OFF + b*Hn + 3] = shw[3];
    }
    __syncthreads();
    float hw0 = shw[0], hw1 = shw[1], hw2 = shw[2], hw3 = shw[3];
    #pragma unroll
    for (int q = 0; q < 4; ++q) {
        int d = q * 256 + tid;
        float ea = hw0 * g_eah[(b*Hn+0)*Dn + d] + hw1 * g_eah[(b*Hn+1)*Dn + d]
                 + hw2 * g_eah[(b*Hn+2)*Dn + d] + hw3 * g_eah[(b*Hn+3)*Dn + d];
        float c = c_out[b*Dn + d];
        const int base = b * 4 * Dn;
        g_feat[base +        d] = c;
        g_feat[base +   Dn + d] = ea;
        g_feat[base + 2*Dn + d] = fabsf(c - ea);
        g_feat[base + 3*Dn + d] = c * ea;
    }
}

// -------- K7: hid_pre = feat @ w1.T  (split-k=4, deterministic) --------
#define M2 64
#define N2 64
#define K2 16
__global__ void __launch_bounds__(256)
k_mlp1(const float* __restrict__ w1) {
    __shared__ float A2[K2][M2];
    __shared__ float B2[K2][N2];
    const int tid = threadIdx.x;
    const int oBase = blockIdx.x * N2;
    const int rBase = blockIdx.y * M2;
    const int kBase = blockIdx.z * 1024;
    const int ty = tid >> 4, tx = tid & 15;
    const int lr = tid >> 2;
    const int lk = (tid & 3) * 4;

    const float* Ag = g_feat + (rBase + lr) * (4*Dn) + kBase + lk;
    const float* Bg = w1     + (oBase + lr) * (4*Dn) + kBase + lk;

    float acc[4][4];
    #pragma unroll
    for (int i = 0; i < 4; ++i)
        #pragma unroll
        for (int j = 0; j < 4; ++j) acc[i][j] = 0.f;

    for (int kt = 0; kt < 1024; kt += K2) {
        float4 a4 = *(const float4*)(Ag + kt);
        float4 b4 = *(const float4*)(Bg + kt);
        __syncthreads();
        A2[lk+0][lr] = a4.x; A2[lk+1][lr] = a4.y; A2[lk+2][lr] = a4.z; A2[lk+3][lr] = a4.w;
        B2[lk+0][lr] = b4.x; B2[lk+1][lr] = b4.y; B2[lk+2][lr] = b4.z; B2[lk+3][lr] = b4.w;
        __syncthreads();
        #pragma unroll
        for (int kk = 0; kk < K2; ++kk) {
            float4 av = *(const float4*)&A2[kk][ty*4];
            float4 bv = *(const float4*)&B2[kk][tx*4];
            float a_[4] = {av.x, av.y, av.z, av.w};
            float b_[4] = {bv.x, bv.y, bv.z, bv.w};
            #pragma unroll
            for (int i = 0; i < 4; ++i)
                #pragma unroll
                for (int j = 0; j < 4; ++j)
                    acc[i][j] = fmaf(a_[i], b_[j], acc[i][j]);
        }
    }
    #pragma unroll
    for (int i = 0; i < 4; ++i)
        #pragma unroll
        for (int j = 0; j < 4; ++j)
            g_hidpart[blockIdx.z * (Bn*Dn) + (rBase + ty*4 + i) * Dn + oBase + tx*4 + j] = acc[i][j];
}

// -------- K8: relu(hid_pre + b1) @ w2.T + b2 -> logits --------
__global__ void k_logits(const float* __restrict__ b1, const float* __restrict__ w2,
                         const float* __restrict__ b2, float* __restrict__ out) {
    const int b = blockIdx.x, tid = threadIdx.x;
    float a0 = 0.f, a1 = 0.f, a2 = 0.f;
    for (int d = tid; d < Dn; d += 128) {
        float hp = g_hidpart[            b*Dn + d] + g_hidpart[  Bn*Dn + b*Dn + d]
                 + g_hidpart[2*Bn*Dn +   b*Dn + d] + g_hidpart[3*Bn*Dn + b*Dn + d]
                 + b1[d];
        hp = fmaxf(hp, 0.f);
        a0 = fmaf(hp, w2[        d], a0);
        a1 = fmaf(hp, w2[  Dn + d], a1);
        a2 = fmaf(hp, w2[2*Dn + d], a2);
    }
    __shared__ float red[128];
    __shared__ float vals[3];
    float pv[3] = {a0, a1, a2};
    for (int i = 0; i < 3; ++i) {
        red[tid] = pv[i]; __syncthreads();
        #pragma unroll
        for (int o = 64; o; o >>= 1) { if (tid < o) red[tid] += red[tid+o]; __syncthreads(); }
        if (!tid) vals[i] = red[0];
        __syncthreads();
    }
    if (!tid) {
        out[b*NLn + 0] = vals[0] + b2[0];
        out[b*NLn + 1] = vals[1] + b2[1];
        out[b*NLn + 2] = vals[2] + b2[2];
    }
}

extern "C" void kernel_launch(void* const* d_in, const int* in_sizes, int n_in,
                              void* d_out, int out_size) {
    const float* c_out  = (const float*)d_in[0];
    const float* e_emb  = (const float*)d_in[1];
    const int*   emask  = (const int*)  d_in[2];
    const float* W_c    = (const float*)d_in[3];
    const float* W_e    = (const float*)d_in[4];
    const float* v      = (const float*)d_in[5];
    const float* gate_w = (const float*)d_in[6];
    const float* gate_b = (const float*)d_in[7];
    const float* w1     = (const float*)d_in[8];
    const float* b1     = (const float*)d_in[9];
    const float* w2     = (const float*)d_in[10];
    const float* b2     = (const float*)d_in[11];
    float* out = (float*)d_out;

    cudaFuncSetAttribute(k_attn_mma, cudaFuncAttributeMaxDynamicSharedMemorySize, SMEM_TOTAL);

    k_prep<<<NBLK_E + NBLK_W + NBLK_S, 256>>>(e_emb, W_e, W_c);
    k_attn_mma<<<dim3(NET, (Bn*Kn)/TCM, Hn), NTHREADS, SMEM_TOTAL>>>(c_out, v);
    k_softmax<<<Bn*Hn, Kn>>>(emask, out);
    k_eah<<<dim3(Dn/256, Bn), 256>>>(e_emb, out);
    k_gate<<<Bn, 256>>>(c_out, gate_w, gate_b, out);
    k_mlp1<<<dim3(Dn/N2, Bn/M2, 4), 256>>>(w1);
    k_logits<<<Bn, 128>>>(b1, w2, b2, out);
}

// round 11
// speedup vs baseline: 1.4286x; 1.2129x over previous
#include <cuda_runtime.h>
#include <cuda_fp16.h>
#include <math.h>
#include <stdint.h>

// Problem shapes
#define Bn  256
#define Kn  64
#define Dn  1024
#define KD  4096                // MLP1 K dim = 4*Dn
#define Hn  4
#define NLn 3

// Output layout in d_out (fp32): logits (B*NL), alpha (B*H*K), head_weights (B*H)
#define ALPHA_OFF 768
#define HW_OFF    (768 + Bn*Hn*Kn)

// HMMA GEMM tiling: CTA 128x128, warp tile 32x64, 8 warps, 2 CTAs/SM
#define TCM 128
#define TCN 128
#define KC  64                  // K elems per chunk (64 fp16 = 128B row)
#define NCHUNK (Dn / KC)        // 16
#define NET    (Dn / TCN)       // 8 e-tiles
#define NTHREADS 256
#define NSTAGE 3

// MLP1 split-k
#define SPLITK 8
#define KSPAN  (KD / SPLITK)    // 512
#define NCHUNK_M (KSPAN / KC)   // 8

typedef unsigned long long u64;

// -------- scratch (static device globals; no allocation allowed) --------
__device__ float g_wcsum[Hn * Dn];
__device__ float g_upart[NET * Bn * Hn * Kn];       // 2 MB
__device__ float g_eah[Bn * Hn * Dn];
__device__ float g_hidpart[SPLITK * Bn * Dn];       // 8 MB
// fp16 operands (single-rounded)
__device__ __half g_Ef[Bn * Kn * Dn];    // 32 MB
__device__ __half g_Wt[Hn * Dn * Dn];    // 8 MB  (transposed: [h][e][d])
__device__ __half g_w1h[Dn * KD];        // 8 MB  (w1 fp16, [N=1024][K=4096])
__device__ __half g_feath[Bn * KD];      // 2 MB  (features fp16, [256][4096])

// -------- helpers --------
__device__ __forceinline__ uint32_t smem_u32(const void* p) {
    uint32_t a;
    asm("{ .reg .u64 t; cvta.to.shared.u64 t, %1; cvt.u32.u64 %0, t; }" : "=r"(a) : "l"(p));
    return a;
}
__device__ __forceinline__ float tanhfast(float x) {
    float y; asm("tanh.approx.f32 %0, %1;" : "=f"(y) : "f"(x)); return y;
}
#define SWZ128(o) ((o) ^ (((o) >> 3) & 0x70))

__device__ __forceinline__ void cp16(uint32_t saddr, const void* gptr) {
    asm volatile("cp.async.cg.shared.global [%0], [%1], 16;"
                 :: "r"(saddr), "l"(__cvta_generic_to_global(gptr)) : "memory");
}
#define CP_COMMIT() asm volatile("cp.async.commit_group;" ::: "memory")
#define CP_WAIT(n)  asm volatile("cp.async.wait_group %0;" :: "n"(n) : "memory")

#define LDSM_X4(r0, r1, r2, r3, addr) \
    asm volatile("ldmatrix.sync.aligned.m8n8.x4.shared.b16 {%0,%1,%2,%3}, [%4];" \
                 : "=r"(r0), "=r"(r1), "=r"(r2), "=r"(r3) : "r"(addr))

#define MMA_F16(c, a, b) \
    asm volatile("mma.sync.aligned.m16n8k16.row.col.f32.f16.f16.f32 " \
                 "{%0,%1,%2,%3}, {%4,%5,%6,%7}, {%8,%9}, {%0,%1,%2,%3};" \
                 : "+f"((c)[0]), "+f"((c)[1]), "+f"((c)[2]), "+f"((c)[3]) \
                 : "r"((a)[0]), "r"((a)[1]), "r"((a)[2]), "r"((a)[3]), \
                   "r"((b)[0]), "r"((b)[1]))

// smem stage layout: A(16KB) + B(16KB) = 32KB per stage
#define OFF_A   0
#define OFF_B   16384
#define STAGE_BYTES 32768
#define SM_EXTRA (NSTAGE * STAGE_BYTES)               // epilogue arrays beyond stages
#define SMEM_TOTAL (NSTAGE * STAGE_BYTES + 4096)      // 102400 -> 2 CTAs/SM

// -------- K0: fused preprocessing (cvtE | cvtW | wcsum | cvtW1) ----
#define NBLK_E  (Bn*Kn*Dn/4/256)      // 16384
#define NBLK_W  ((Dn/32)*(Dn/32)*Hn)  // 4096
#define NBLK_S  (Hn*Dn*32/256)        // 512
#define NBLK_W1 (Dn*KD/4/256)         // 4096
__global__ void k_prep(const float* __restrict__ e, const float* __restrict__ W,
                       const float* __restrict__ W_c, const float* __restrict__ w1) {
    __shared__ float t[32][33];
    const int bx = blockIdx.x;
    const int tid = threadIdx.x;
    if (bx < NBLK_E) {
        // convert e_emb to fp16
        size_t i = (size_t)bx * 256 + tid;   // over float4s
        float4 x = ((const float4*)e)[i];
        __half h0 = __float2half_rn(x.x), h1 = __float2half_rn(x.y);
        __half h2 = __float2half_rn(x.z), h3 = __float2half_rn(x.w);
        ((__half2*)g_Ef)[2*i    ] = __halves2half2(h0, h1);
        ((__half2*)g_Ef)[2*i + 1] = __halves2half2(h2, h3);
    } else if (bx < NBLK_E + NBLK_W) {
        // transpose W_e[h][d][e] -> Wt[h][e][d] fp16
        const int b  = bx - NBLK_E;
        const int h  = b >> 10;
        const int dB = ((b & 1023) >> 5) * 32;
        const int eB = (b & 31) * 32;
        const int lx = tid & 31, ly = tid >> 5;  // 32 x 8
        #pragma unroll
        for (int r = 0; r < 4; ++r)
            t[ly + 8*r][lx] = W[((size_t)h*Dn + dB + ly + 8*r) * Dn + eB + lx];
        __syncthreads();
        #pragma unroll
        for (int r = 0; r < 4; ++r) {
            float x = t[lx][ly + 8*r];
            size_t oi = ((size_t)h*Dn + eB + ly + 8*r) * Dn + dB + lx;
            g_Wt[oi] = __float2half_rn(x);
        }
    } else if (bx < NBLK_E + NBLK_W + NBLK_S) {
        // Wc_sum[h,d] = sum_e W_c[h,d,e]
        int warp = (((bx - NBLK_E - NBLK_W) << 8) + tid) >> 5;
        int lane = tid & 31;
        const float* p = W_c + (size_t)warp * Dn;
        float s = 0.f;
        #pragma unroll 8
        for (int j = lane; j < Dn; j += 32) s += p[j];
        #pragma unroll
        for (int o = 16; o; o >>= 1) s += __shfl_down_sync(0xffffffffu, s, o);
        if (!lane) g_wcsum[warp] = s;
    } else {
        // convert w1 to fp16 (row-major [1024][4096], no transpose needed)
        size_t i = (size_t)(bx - NBLK_E - NBLK_W - NBLK_S) * 256 + tid;
        float4 x = ((const float4*)w1)[i];
        __half h0 = __float2half_rn(x.x), h1 = __float2half_rn(x.y);
        __half h2 = __float2half_rn(x.z), h3 = __float2half_rn(x.w);
        ((__half2*)g_w1h)[2*i    ] = __halves2half2(h0, h1);
        ((__half2*)g_w1h)[2*i + 1] = __halves2half2(h2, h3);
    }
}

// -------- K2: HMMA fused  P = E @ Wt^T (fp16);  u = sum_e tanh(cp+P)*v ----
__global__ void __launch_bounds__(NTHREADS, 2)
k_attn_mma(const float* __restrict__ c_out, const float* __restrict__ v)
{
    extern __shared__ char smem[];
    const uint32_t sb = smem_u32(smem);
    const int tid   = threadIdx.x;
    const int wid   = tid >> 5;
    const int lane  = tid & 31;
    const int warpM = wid >> 1;     // 0..3 (32 rows each)
    const int warpN = wid & 1;      // 0..1 (64 cols each)

    const int et      = blockIdx.x;          // 0..7
    const int rowBase = blockIdx.y * TCM;
    const int h       = blockIdx.z;          // 0..3
    const int eBase   = et * TCN;

    const __half* Ap = g_Ef + (size_t)rowBase * Dn;
    const __half* Bp = g_Wt + ((size_t)h * Dn + eBase) * Dn;

    float* s_cce0 = (float*)(smem + SM_EXTRA);       // 128
    float* s_cce1 = s_cce0 + TCN;                    // 128
    float* s_vv   = s_cce1 + TCN;                    // 128
    float* s_red  = s_vv + TCN;                      // [128][2]

    const int b0 = rowBase >> 6;
    {
        int e0 = eBase + (tid & 127);
        float wc0 = g_wcsum[h * Dn + e0];
        if (tid < 128) {
            s_cce0[tid] = c_out[b0 * Dn + e0] * wc0;
            s_vv[tid]   = v[h * Dn + e0];
        } else {
            s_cce1[tid - 128] = c_out[(b0 + 1) * Dn + e0] * wc0;
        }
    }

    int arow[4], ac16[4]; uint32_t aso[4];
    #pragma unroll
    for (int i = 0; i < 4; ++i) {
        int seg = tid + i * NTHREADS;
        arow[i] = seg >> 3; ac16[i] = seg & 7;
        aso[i] = SWZ128((uint32_t)(arow[i] * 128 + ac16[i] * 16));
    }

    float acc[2][8][4];
    #pragma unroll
    for (int mt = 0; mt < 2; ++mt)
        #pragma unroll
        for (int nt = 0; nt < 8; ++nt)
            #pragma unroll
            for (int j = 0; j < 4; ++j) acc[mt][nt][j] = 0.f;

    const uint32_t aRowB = (uint32_t)((warpM * 32 + (lane & 15)) * 128);
    const uint32_t bRowB = (uint32_t)((warpN * 64 + (lane & 15)) * 128);
    const uint32_t colSel = (uint32_t)((lane >> 4) * 16);

    #pragma unroll
    for (int pc = 0; pc < 2; ++pc) {
        const uint32_t st = sb + pc * STAGE_BYTES;
        const int dB = pc * KC;
        #pragma unroll
        for (int i = 0; i < 4; ++i) {
            cp16(st + OFF_A + aso[i], Ap + (size_t)arow[i] * Dn + dB + ac16[i] * 8);
            cp16(st + OFF_B + aso[i], Bp + (size_t)arow[i] * Dn + dB + ac16[i] * 8);
        }
        CP_COMMIT();
    }

    int stage = 0;
    for (int c = 0; c < NCHUNK; ++c) {
        if (c + 2 < NCHUNK) { CP_WAIT(1); } else { CP_WAIT(0); }
        __syncthreads();

        // early prefetch of chunk c+2 (slot consumed at chunk c-1)
        if (c + 2 < NCHUNK) {
            int ns = stage + 2; if (ns >= NSTAGE) ns -= NSTAGE;
            const uint32_t stn = sb + ns * STAGE_BYTES;
            const int dB = (c + 2) * KC;
            #pragma unroll
            for (int i = 0; i < 4; ++i) {
                cp16(stn + OFF_A + aso[i], Ap + (size_t)arow[i] * Dn + dB + ac16[i] * 8);
                cp16(stn + OFF_B + aso[i], Bp + (size_t)arow[i] * Dn + dB + ac16[i] * 8);
            }
            CP_COMMIT();
        }

        const uint32_t st = sb + stage * STAGE_BYTES;
        #pragma unroll
        for (int ks = 0; ks < KC / 16; ++ks) {
            const uint32_t kcol = ks * 32 + colSel;
            uint32_t af[2][4];
            #pragma unroll
            for (int mt = 0; mt < 2; ++mt) {
                uint32_t off = SWZ128(aRowB + (uint32_t)(mt * 16 * 128) + kcol);
                LDSM_X4(af[mt][0], af[mt][1], af[mt][2], af[mt][3], st + OFF_A + off);
            }
            uint32_t bf[8][2];
            #pragma unroll
            for (int p = 0; p < 4; ++p) {
                uint32_t off = SWZ128(bRowB + (uint32_t)(p * 16 * 128) + kcol);
                uint32_t r0, r1, r2, r3;
                LDSM_X4(r0, r1, r2, r3, st + OFF_B + off);
                bf[2*p][0] = r0; bf[2*p][1] = r2;
                bf[2*p+1][0] = r1; bf[2*p+1][1] = r3;
            }
            #pragma unroll
            for (int mt = 0; mt < 2; ++mt)
                #pragma unroll
                for (int nt = 0; nt < 8; ++nt)
                    MMA_F16(acc[mt][nt], af[mt], bf[nt]);
        }
        if (++stage == NSTAGE) stage = 0;
    }

    const int gRow = lane >> 2;
    const int c2   = (lane & 3) * 2;
    const float* cce = (warpM >= 2) ? s_cce1 : s_cce0;

    #pragma unroll
    for (int mt = 0; mt < 2; ++mt) {
        #pragma unroll
        for (int h2 = 0; h2 < 2; ++h2) {
            float p = 0.f;
            #pragma unroll
            for (int nt = 0; nt < 8; ++nt) {
                int e0 = warpN * 64 + nt * 8 + c2;
                float v0 = acc[mt][nt][h2 * 2 + 0];
                float v1 = acc[mt][nt][h2 * 2 + 1];
                p += tanhfast(v0 + cce[e0    ]) * s_vv[e0    ];
                p += tanhfast(v1 + cce[e0 + 1]) * s_vv[e0 + 1];
            }
            p += __shfl_xor_sync(0xffffffffu, p, 1);
            p += __shfl_xor_sync(0xffffffffu, p, 2);
            if ((lane & 3) == 0) {
                int lrow2 = warpM * 32 + mt * 16 + h2 * 8 + gRow;
                s_red[lrow2 * 2 + warpN] = p;
            }
        }
    }
    __syncthreads();

    if (tid < 128) {
        float s = s_red[tid*2] + s_red[tid*2+1];
        int rg = rowBase + tid;
        int bb = rg >> 6, kk = rg & 63;
        g_upart[et * (Bn * Hn * Kn) + ((bb * Hn + h) << 6) + kk] = s;
    }
}

// -------- K4: fused softmax + e_att_heads (reads fp16 E) --------
// grid: (Dn/256, Bn). Each block recomputes softmax for its b (deterministic).
__global__ void k_eah(const int* __restrict__ mask, float* __restrict__ out) {
    const int b = blockIdx.y, tid = threadIdx.x;
    const int d = blockIdx.x * 256 + tid;
    const int hh = tid >> 6, kk = tid & 63;

    __shared__ float red[256];
    __shared__ float sal[256];

    // u[b, hh, kk] = sum of partials; mask
    float s = 0.f;
    #pragma unroll
    for (int nt = 0; nt < NET; ++nt)
        s += g_upart[nt * (Bn*Hn*Kn) + ((b * Hn + hh) << 6) + kk];
    if (mask[b * Kn + kk] == 0) s = __int_as_float(0xff800000);

    // softmax over k within each 64-thread h-group
    red[tid] = s; __syncthreads();
    #pragma unroll
    for (int o = 32; o; o >>= 1) {
        if ((tid & 63) < o) red[tid] = fmaxf(red[tid], red[tid + o]);
        __syncthreads();
    }
    float mx = red[hh << 6]; __syncthreads();
    float ex = __expf(s - mx);
    red[tid] = ex; __syncthreads();
    #pragma unroll
    for (int o = 32; o; o >>= 1) {
        if ((tid & 63) < o) red[tid] += red[tid + o];
        __syncthreads();
    }
    float al = ex / red[hh << 6];
    sal[tid] = al;
    if (blockIdx.x == 0) out[ALPHA_OFF + b * (Hn*Kn) + tid] = al;
    __syncthreads();

    // e_att_heads from fp16 E
    float a0 = 0.f, a1 = 0.f, a2 = 0.f, a3 = 0.f;
    const __half* ep = g_Ef + (size_t)b * Kn * Dn + d;
    #pragma unroll 8
    for (int k = 0; k < Kn; ++k) {
        float ev = __half2float(ep[k * Dn]);
        a0 = fmaf(sal[k      ], ev, a0);
        a1 = fmaf(sal[64  + k], ev, a1);
        a2 = fmaf(sal[128 + k], ev, a2);
        a3 = fmaf(sal[192 + k], ev, a3);
    }
    g_eah[(b*Hn + 0) * Dn + d] = a0;
    g_eah[(b*Hn + 1) * Dn + d] = a1;
    g_eah[(b*Hn + 2) * Dn + d] = a2;
    g_eah[(b*Hn + 3) * Dn + d] = a3;
}

// -------- K5: gate logits + softmax over H + fp16 feature vector --------
__global__ void k_gate(const float* __restrict__ c_out, const float* __restrict__ gate_w,
                       const float* __restrict__ gate_b, float* __restrict__ out) {
    const int b = blockIdx.x, tid = threadIdx.x;
    float pv[5] = {0.f, 0.f, 0.f, 0.f, 0.f};
    for (int d = tid; d < Dn; d += 256) {
        float gwc = gate_w[d], gwe = gate_w[Dn + d];
        pv[0] = fmaf(c_out[b*Dn + d], gwc, pv[0]);
        pv[1] = fmaf(g_eah[(b*Hn + 0)*Dn + d], gwe, pv[1]);
        pv[2] = fmaf(g_eah[(b*Hn + 1)*Dn + d], gwe, pv[2]);
        pv[3] = fmaf(g_eah[(b*Hn + 2)*Dn + d], gwe, pv[3]);
        pv[4] = fmaf(g_eah[(b*Hn + 3)*Dn + d], gwe, pv[4]);
    }
    __shared__ float red[256];
    __shared__ float vals[5];
    __shared__ float shw[4];
    for (int i = 0; i < 5; ++i) {
        red[tid] = pv[i]; __syncthreads();
        #pragma unroll
        for (int o = 128; o; o >>= 1) { if (tid < o) red[tid] += red[tid+o]; __syncthreads(); }
        if (!tid) vals[i] = red[0];
        __syncthreads();
    }
    if (!tid) {
        float gb = gate_b[0];
        float g0 = vals[0] + vals[1] + gb, g1 = vals[0] + vals[2] + gb;
        float g2 = vals[0] + vals[3] + gb, g3 = vals[0] + vals[4] + gb;
        float mx = fmaxf(fmaxf(g0, g1), fmaxf(g2, g3));
        float e0 = __expf(g0 - mx), e1 = __expf(g1 - mx);
        float e2 = __expf(g2 - mx), e3 = __expf(g3 - mx);
        float inv = 1.f / (e0 + e1 + e2 + e3);
        shw[0] = e0*inv; shw[1] = e1*inv; shw[2] = e2*inv; shw[3] = e3*inv;
        out[HW_OFF + b*Hn + 0] = shw[0]; out[HW_OFF + b*Hn + 1] = shw[1];
        out[HW_OFF + b*Hn + 2] = shw[2]; out[HW_OFF + b*Hn + 3] = shw[3];
    }
    __syncthreads();
    float hw0 = shw[0], hw1 = shw[1], hw2 = shw[2], hw3 = shw[3];
    #pragma unroll
    for (int q = 0; q < 4; ++q) {
        int d = q * 256 + tid;
        float ea = hw0 * g_eah[(b*Hn+0)*Dn + d] + hw1 * g_eah[(b*Hn+1)*Dn + d]
                 + hw2 * g_eah[(b*Hn+2)*Dn + d] + hw3 * g_eah[(b*Hn+3)*Dn + d];
        float c = c_out[b*Dn + d];
        const size_t base = (size_t)b * KD;
        g_feath[base +        d] = __float2half_rn(c);
        g_feath[base +   Dn + d] = __float2half_rn(ea);
        g_feath[base + 2*Dn + d] = __float2half_rn(fabsf(c - ea));
        g_feath[base + 3*Dn + d] = __float2half_rn(c * ea);
    }
}

// -------- K7: hid_part = feat @ w1.T via HMMA fp16 (split-k=8) --------
// grid (Dn/TCN=8, Bn/TCM=2, SPLITK=8); same skeleton as k_attn_mma
__global__ void __launch_bounds__(NTHREADS, 2)
k_mlp1() {
    extern __shared__ char smem[];
    const uint32_t sb = smem_u32(smem);
    const int tid   = threadIdx.x;
    const int wid   = tid >> 5;
    const int lane  = tid & 31;
    const int warpM = wid >> 1;
    const int warpN = wid & 1;

    const int oBase   = blockIdx.x * TCN;    // hid-col base
    const int rowBase = blockIdx.y * TCM;    // batch-row base
    const int z       = blockIdx.z;          // split-k slab
    const int kBase   = z * KSPAN;

    const __half* Ap = g_feath + (size_t)rowBase * KD + kBase;
    const __half* Bp = g_w1h   + (size_t)oBase * KD + kBase;

    int arow[4], ac16[4]; uint32_t aso[4];
    #pragma unroll
    for (int i = 0; i < 4; ++i) {
        int seg = tid + i * NTHREADS;
        arow[i] = seg >> 3; ac16[i] = seg & 7;
        aso[i] = SWZ128((uint32_t)(arow[i] * 128 + ac16[i] * 16));
    }

    float acc[2][8][4];
    #pragma unroll
    for (int mt = 0; mt < 2; ++mt)
        #pragma unroll
        for (int nt = 0; nt < 8; ++nt)
            #pragma unroll
            for (int j = 0; j < 4; ++j) acc[mt][nt][j] = 0.f;

    const uint32_t aRowB = (uint32_t)((warpM * 32 + (lane & 15)) * 128);
    const uint32_t bRowB = (uint32_t)((warpN * 64 + (lane & 15)) * 128);
    const uint32_t colSel = (uint32_t)((lane >> 4) * 16);

    #pragma unroll
    for (int pc = 0; pc < 2; ++pc) {
        const uint32_t st = sb + pc * STAGE_BYTES;
        const int dB = pc * KC;
        #pragma unroll
        for (int i = 0; i < 4; ++i) {
            cp16(st + OFF_A + aso[i], Ap + (size_t)arow[i] * KD + dB + ac16[i] * 8);
            cp16(st + OFF_B + aso[i], Bp + (size_t)arow[i] * KD + dB + ac16[i] * 8);
        }
        CP_COMMIT();
    }

    int stage = 0;
    for (int c = 0; c < NCHUNK_M; ++c) {
        if (c + 2 < NCHUNK_M) { CP_WAIT(1); } else { CP_WAIT(0); }
        __syncthreads();

        if (c + 2 < NCHUNK_M) {
            int ns = stage + 2; if (ns >= NSTAGE) ns -= NSTAGE;
            const uint32_t stn = sb + ns * STAGE_BYTES;
            const int dB = (c + 2) * KC;
            #pragma unroll
            for (int i = 0; i < 4; ++i) {
                cp16(stn + OFF_A + aso[i], Ap + (size_t)arow[i] * KD + dB + ac16[i] * 8);
                cp16(stn + OFF_B + aso[i], Bp + (size_t)arow[i] * KD + dB + ac16[i] * 8);
            }
            CP_COMMIT();
        }

        const uint32_t st = sb + stage * STAGE_BYTES;
        #pragma unroll
        for (int ks = 0; ks < KC / 16; ++ks) {
            const uint32_t kcol = ks * 32 + colSel;
            uint32_t af[2][4];
            #pragma unroll
            for (int mt = 0; mt < 2; ++mt) {
                uint32_t off = SWZ128(aRowB + (uint32_t)(mt * 16 * 128) + kcol);
                LDSM_X4(af[mt][0], af[mt][1], af[mt][2], af[mt][3], st + OFF_A + off);
            }
            uint32_t bf[8][2];
            #pragma unroll
            for (int p = 0; p < 4; ++p) {
                uint32_t off = SWZ128(bRowB + (uint32_t)(p * 16 * 128) + kcol);
                uint32_t r0, r1, r2, r3;
                LDSM_X4(r0, r1, r2, r3, st + OFF_B + off);
                bf[2*p][0] = r0; bf[2*p][1] = r2;
                bf[2*p+1][0] = r1; bf[2*p+1][1] = r3;
            }
            #pragma unroll
            for (int mt = 0; mt < 2; ++mt)
                #pragma unroll
                for (int nt = 0; nt < 8; ++nt)
                    MMA_F16(acc[mt][nt], af[mt], bf[nt]);
        }
        if (++stage == NSTAGE) stage = 0;
    }

    // epilogue: write fp32 partials to slab z
    float* slab = g_hidpart + (size_t)z * (Bn * Dn);
    const int gRow = lane >> 2;
    const int gCol = (lane & 3) * 2;
    #pragma unroll
    for (int mt = 0; mt < 2; ++mt)
        #pragma unroll
        for (int h2 = 0; h2 < 2; ++h2) {
            int row = rowBase + warpM * 32 + mt * 16 + h2 * 8 + gRow;
            #pragma unroll
            for (int nt = 0; nt < 8; ++nt) {
                int col = oBase + warpN * 64 + nt * 8 + gCol;
                float2 val = make_float2(acc[mt][nt][h2*2], acc[mt][nt][h2*2+1]);
                *(float2*)&slab[(size_t)row * Dn + col] = val;
            }
        }
}

// -------- K8: relu(sum hid_parts + b1) @ w2.T + b2 -> logits --------
__global__ void k_logits(const float* __restrict__ b1, const float* __restrict__ w2,
                         const float* __restrict__ b2, float* __restrict__ out) {
    const int b = blockIdx.x, tid = threadIdx.x;
    float a0 = 0.f, a1 = 0.f, a2 = 0.f;
    for (int d = tid; d < Dn; d += 128) {
        float hp = b1[d];
        #pragma unroll
        for (int zz = 0; zz < SPLITK; ++zz)
            hp += g_hidpart[(size_t)zz * (Bn*Dn) + b*Dn + d];
        hp = fmaxf(hp, 0.f);
        a0 = fmaf(hp, w2[        d], a0);
        a1 = fmaf(hp, w2[  Dn + d], a1);
        a2 = fmaf(hp, w2[2*Dn + d], a2);
    }
    __shared__ float red[128];
    __shared__ float vals[3];
    float pv[3] = {a0, a1, a2};
    for (int i = 0; i < 3; ++i) {
        red[tid] = pv[i]; __syncthreads();
        #pragma unroll
        for (int o = 64; o; o >>= 1) { if (tid < o) red[tid] += red[tid+o]; __syncthreads(); }
        if (!tid) vals[i] = red[0];
        __syncthreads();
    }
    if (!tid) {
        out[b*NLn + 0] = vals[0] + b2[0];
        out[b*NLn + 1] = vals[1] + b2[1];
        out[b*NLn + 2] = vals[2] + b2[2];
    }
}

extern "C" void kernel_launch(void* const* d_in, const int* in_sizes, int n_in,
                              void* d_out, int out_size) {
    const float* c_out  = (const float*)d_in[0];
    const float* e_emb  = (const float*)d_in[1];
    const int*   emask  = (const int*)  d_in[2];
    const float* W_c    = (const float*)d_in[3];
    const float* W_e    = (const float*)d_in[4];
    const float* v      = (const float*)d_in[5];
    const float* gate_w = (const float*)d_in[6];
    const float* gate_b = (const float*)d_in[7];
    const float* w1     = (const float*)d_in[8];
    const float* b1     = (const float*)d_in[9];
    const float* w2     = (const float*)d_in[10];
    const float* b2     = (const float*)d_in[11];
    float* out = (float*)d_out;

    cudaFuncSetAttribute(k_attn_mma, cudaFuncAttributeMaxDynamicSharedMemorySize, SMEM_TOTAL);
    cudaFuncSetAttribute(k_mlp1, cudaFuncAttributeMaxDynamicSharedMemorySize, SMEM_TOTAL);

    k_prep<<<NBLK_E + NBLK_W + NBLK_S + NBLK_W1, 256>>>(e_emb, W_e, W_c, w1);
    k_attn_mma<<<dim3(NET, (Bn*Kn)/TCM, Hn), NTHREADS, SMEM_TOTAL>>>(c_out, v);
    k_eah<<<dim3(Dn/256, Bn), 256>>>(emask, out);
    k_gate<<<Bn, 256>>>(c_out, gate_w, gate_b, out);
    k_mlp1<<<dim3(Dn/TCN, Bn/TCM, SPLITK), NTHREADS, SMEM_TOTAL>>>();
    k_logits<<<Bn, 128>>>(b1, w2, b2, out);
}

// round 12
// speedup vs baseline: 1.4441x; 1.0109x over previous
#include <cuda_runtime.h>
#include <cuda_fp16.h>
#include <math.h>
#include <stdint.h>

// Problem shapes
#define Bn  256
#define Kn  64
#define Dn  1024
#define KD  4096                // MLP1 K dim = 4*Dn
#define Hn  4
#define NLn 3

// Output layout in d_out (fp32): logits (B*NL), alpha (B*H*K), head_weights (B*H)
#define ALPHA_OFF 768
#define HW_OFF    (768 + Bn*Hn*Kn)

// HMMA GEMM tiling: CTA 128x128, warp tile 32x64, 8 warps, 2 CTAs/SM
#define TCM 128
#define TCN 128
#define KC  64                  // K elems per chunk (64 fp16 = 128B row)
#define NCHUNK (Dn / KC)        // 16
#define NET    (Dn / TCN)       // 8 e-tiles
#define NTHREADS 256
#define NSTAGE 3

// MLP1 split-k
#define SPLITK 8
#define KSPAN  (KD / SPLITK)    // 512
#define NCHUNK_M (KSPAN / KC)   // 8

typedef unsigned long long u64;

// -------- scratch (static device globals; no allocation allowed) --------
__device__ float g_wcsum[Hn * Dn];
__device__ float g_upart[NET * Bn * Hn * Kn];       // 2 MB
__device__ float g_hidpart[SPLITK * Bn * Dn];       // 8 MB
// fp16 operands (single-rounded)
__device__ __half g_Ef[Bn * Kn * Dn];    // 32 MB
__device__ __half g_Wt[Hn * Dn * Dn];    // 8 MB  (transposed: [h][e][d])
__device__ __half g_w1h[Dn * KD];        // 8 MB  (w1 fp16, [N=1024][K=4096])
__device__ __half g_feath[Bn * KD];      // 2 MB  (features fp16, [256][4096])

// -------- helpers --------
__device__ __forceinline__ uint32_t smem_u32(const void* p) {
    uint32_t a;
    asm("{ .reg .u64 t; cvta.to.shared.u64 t, %1; cvt.u32.u64 %0, t; }" : "=r"(a) : "l"(p));
    return a;
}
__device__ __forceinline__ float tanhfast(float x) {
    float y; asm("tanh.approx.f32 %0, %1;" : "=f"(y) : "f"(x)); return y;
}
#define SWZ128(o) ((o) ^ (((o) >> 3) & 0x70))

__device__ __forceinline__ void cp16(uint32_t saddr, const void* gptr) {
    asm volatile("cp.async.cg.shared.global [%0], [%1], 16;"
                 :: "r"(saddr), "l"(__cvta_generic_to_global(gptr)) : "memory");
}
#define CP_COMMIT() asm volatile("cp.async.commit_group;" ::: "memory")
#define CP_WAIT(n)  asm volatile("cp.async.wait_group %0;" :: "n"(n) : "memory")

#define LDSM_X4(r0, r1, r2, r3, addr) \
    asm volatile("ldmatrix.sync.aligned.m8n8.x4.shared.b16 {%0,%1,%2,%3}, [%4];" \
                 : "=r"(r0), "=r"(r1), "=r"(r2), "=r"(r3) : "r"(addr))

#define MMA_F16(c, a, b) \
    asm volatile("mma.sync.aligned.m16n8k16.row.col.f32.f16.f16.f32 " \
                 "{%0,%1,%2,%3}, {%4,%5,%6,%7}, {%8,%9}, {%0,%1,%2,%3};" \
                 : "+f"((c)[0]), "+f"((c)[1]), "+f"((c)[2]), "+f"((c)[3]) \
                 : "r"((a)[0]), "r"((a)[1]), "r"((a)[2]), "r"((a)[3]), \
                   "r"((b)[0]), "r"((b)[1]))

// smem stage layout: A(16KB) + B(16KB) = 32KB per stage
#define OFF_A   0
#define OFF_B   16384
#define STAGE_BYTES 32768
#define SM_EXTRA (NSTAGE * STAGE_BYTES)               // epilogue arrays beyond stages
#define SMEM_TOTAL (NSTAGE * STAGE_BYTES + 4096)      // 102400 -> 2 CTAs/SM

// -------- K0: fused preprocessing (cvtE | cvtW | wcsum | cvtW1) ----
#define NBLK_E  (Bn*Kn*Dn/4/256)      // 16384
#define NBLK_W  ((Dn/32)*(Dn/32)*Hn)  // 4096
#define NBLK_S  (Hn*Dn*32/256)        // 512
#define NBLK_W1 (Dn*KD/4/256)         // 4096
__global__ void k_prep(const float* __restrict__ e, const float* __restrict__ W,
                       const float* __restrict__ W_c, const float* __restrict__ w1) {
    __shared__ float t[32][33];
    const int bx = blockIdx.x;
    const int tid = threadIdx.x;
    if (bx < NBLK_E) {
        size_t i = (size_t)bx * 256 + tid;   // over float4s
        float4 x = ((const float4*)e)[i];
        __half h0 = __float2half_rn(x.x), h1 = __float2half_rn(x.y);
        __half h2 = __float2half_rn(x.z), h3 = __float2half_rn(x.w);
        ((__half2*)g_Ef)[2*i    ] = __halves2half2(h0, h1);
        ((__half2*)g_Ef)[2*i + 1] = __halves2half2(h2, h3);
    } else if (bx < NBLK_E + NBLK_W) {
        const int b  = bx - NBLK_E;
        const int h  = b >> 10;
        const int dB = ((b & 1023) >> 5) * 32;
        const int eB = (b & 31) * 32;
        const int lx = tid & 31, ly = tid >> 5;  // 32 x 8
        #pragma unroll
        for (int r = 0; r < 4; ++r)
            t[ly + 8*r][lx] = W[((size_t)h*Dn + dB + ly + 8*r) * Dn + eB + lx];
        __syncthreads();
        #pragma unroll
        for (int r = 0; r < 4; ++r) {
            float x = t[lx][ly + 8*r];
            size_t oi = ((size_t)h*Dn + eB + ly + 8*r) * Dn + dB + lx;
            g_Wt[oi] = __float2half_rn(x);
        }
    } else if (bx < NBLK_E + NBLK_W + NBLK_S) {
        int warp = (((bx - NBLK_E - NBLK_W) << 8) + tid) >> 5;
        int lane = tid & 31;
        const float* p = W_c + (size_t)warp * Dn;
        float s = 0.f;
        #pragma unroll 8
        for (int j = lane; j < Dn; j += 32) s += p[j];
        #pragma unroll
        for (int o = 16; o; o >>= 1) s += __shfl_down_sync(0xffffffffu, s, o);
        if (!lane) g_wcsum[warp] = s;
    } else {
        size_t i = (size_t)(bx - NBLK_E - NBLK_W - NBLK_S) * 256 + tid;
        float4 x = ((const float4*)w1)[i];
        __half h0 = __float2half_rn(x.x), h1 = __float2half_rn(x.y);
        __half h2 = __float2half_rn(x.z), h3 = __float2half_rn(x.w);
        ((__half2*)g_w1h)[2*i    ] = __halves2half2(h0, h1);
        ((__half2*)g_w1h)[2*i + 1] = __halves2half2(h2, h3);
    }
}

// -------- K2: HMMA fused  P = E @ Wt^T (fp16);  u = sum_e tanh(cp+P)*v ----
__global__ void __launch_bounds__(NTHREADS, 2)
k_attn_mma(const float* __restrict__ c_out, const float* __restrict__ v)
{
    extern __shared__ char smem[];
    const uint32_t sb = smem_u32(smem);
    const int tid   = threadIdx.x;
    const int wid   = tid >> 5;
    const int lane  = tid & 31;
    const int warpM = wid >> 1;
    const int warpN = wid & 1;

    const int et      = blockIdx.x;
    const int rowBase = blockIdx.y * TCM;
    const int h       = blockIdx.z;
    const int eBase   = et * TCN;

    const __half* Ap = g_Ef + (size_t)rowBase * Dn;
    const __half* Bp = g_Wt + ((size_t)h * Dn + eBase) * Dn;

    float* s_cce0 = (float*)(smem + SM_EXTRA);
    float* s_cce1 = s_cce0 + TCN;
    float* s_vv   = s_cce1 + TCN;
    float* s_red  = s_vv + TCN;

    const int b0 = rowBase >> 6;
    {
        int e0 = eBase + (tid & 127);
        float wc0 = g_wcsum[h * Dn + e0];
        if (tid < 128) {
            s_cce0[tid] = c_out[b0 * Dn + e0] * wc0;
            s_vv[tid]   = v[h * Dn + e0];
        } else {
            s_cce1[tid - 128] = c_out[(b0 + 1) * Dn + e0] * wc0;
        }
    }

    int arow[4], ac16[4]; uint32_t aso[4];
    #pragma unroll
    for (int i = 0; i < 4; ++i) {
        int seg = tid + i * NTHREADS;
        arow[i] = seg >> 3; ac16[i] = seg & 7;
        aso[i] = SWZ128((uint32_t)(arow[i] * 128 + ac16[i] * 16));
    }

    float acc[2][8][4];
    #pragma unroll
    for (int mt = 0; mt < 2; ++mt)
        #pragma unroll
        for (int nt = 0; nt < 8; ++nt)
            #pragma unroll
            for (int j = 0; j < 4; ++j) acc[mt][nt][j] = 0.f;

    const uint32_t aRowB = (uint32_t)((warpM * 32 + (lane & 15)) * 128);
    const uint32_t bRowB = (uint32_t)((warpN * 64 + (lane & 15)) * 128);
    const uint32_t colSel = (uint32_t)((lane >> 4) * 16);

    #pragma unroll
    for (int pc = 0; pc < 2; ++pc) {
        const uint32_t st = sb + pc * STAGE_BYTES;
        const int dB = pc * KC;
        #pragma unroll
        for (int i = 0; i < 4; ++i) {
            cp16(st + OFF_A + aso[i], Ap + (size_t)arow[i] * Dn + dB + ac16[i] * 8);
            cp16(st + OFF_B + aso[i], Bp + (size_t)arow[i] * Dn + dB + ac16[i] * 8);
        }
        CP_COMMIT();
    }

    int stage = 0;
    for (int c = 0; c < NCHUNK; ++c) {
        if (c + 2 < NCHUNK) { CP_WAIT(1); } else { CP_WAIT(0); }
        __syncthreads();

        if (c + 2 < NCHUNK) {
            int ns = stage + 2; if (ns >= NSTAGE) ns -= NSTAGE;
            const uint32_t stn = sb + ns * STAGE_BYTES;
            const int dB = (c + 2) * KC;
            #pragma unroll
            for (int i = 0; i < 4; ++i) {
                cp16(stn + OFF_A + aso[i], Ap + (size_t)arow[i] * Dn + dB + ac16[i] * 8);
                cp16(stn + OFF_B + aso[i], Bp + (size_t)arow[i] * Dn + dB + ac16[i] * 8);
            }
            CP_COMMIT();
        }

        const uint32_t st = sb + stage * STAGE_BYTES;
        #pragma unroll
        for (int ks = 0; ks < KC / 16; ++ks) {
            const uint32_t kcol = ks * 32 + colSel;
            uint32_t af[2][4];
            #pragma unroll
            for (int mt = 0; mt < 2; ++mt) {
                uint32_t off = SWZ128(aRowB + (uint32_t)(mt * 16 * 128) + kcol);
                LDSM_X4(af[mt][0], af[mt][1], af[mt][2], af[mt][3], st + OFF_A + off);
            }
            uint32_t bf[8][2];
            #pragma unroll
            for (int p = 0; p < 4; ++p) {
                uint32_t off = SWZ128(bRowB + (uint32_t)(p * 16 * 128) + kcol);
                uint32_t r0, r1, r2, r3;
                LDSM_X4(r0, r1, r2, r3, st + OFF_B + off);
                bf[2*p][0] = r0; bf[2*p][1] = r2;
                bf[2*p+1][0] = r1; bf[2*p+1][1] = r3;
            }
            #pragma unroll
            for (int mt = 0; mt < 2; ++mt)
                #pragma unroll
                for (int nt = 0; nt < 8; ++nt)
                    MMA_F16(acc[mt][nt], af[mt], bf[nt]);
        }
        if (++stage == NSTAGE) stage = 0;
    }

    const int gRow = lane >> 2;
    const int c2   = (lane & 3) * 2;
    const float* cce = (warpM >= 2) ? s_cce1 : s_cce0;

    #pragma unroll
    for (int mt = 0; mt < 2; ++mt) {
        #pragma unroll
        for (int h2 = 0; h2 < 2; ++h2) {
            float p = 0.f;
            #pragma unroll
            for (int nt = 0; nt < 8; ++nt) {
                int e0 = warpN * 64 + nt * 8 + c2;
                float v0 = acc[mt][nt][h2 * 2 + 0];
                float v1 = acc[mt][nt][h2 * 2 + 1];
                p += tanhfast(v0 + cce[e0    ]) * s_vv[e0    ];
                p += tanhfast(v1 + cce[e0 + 1]) * s_vv[e0 + 1];
            }
            p += __shfl_xor_sync(0xffffffffu, p, 1);
            p += __shfl_xor_sync(0xffffffffu, p, 2);
            if ((lane & 3) == 0) {
                int lrow2 = warpM * 32 + mt * 16 + h2 * 8 + gRow;
                s_red[lrow2 * 2 + warpN] = p;
            }
        }
    }
    __syncthreads();

    if (tid < 128) {
        float s = s_red[tid*2] + s_red[tid*2+1];
        int rg = rowBase + tid;
        int bb = rg >> 6, kk = rg & 63;
        g_upart[et * (Bn * Hn * Kn) + ((bb * Hn + h) << 6) + kk] = s;
    }
}

// -------- K4: FUSED softmax + e_att_heads(smem) + gate + head_wts + feat ----
// grid: Bn blocks x 1024 threads; one block per batch row.
__global__ void __launch_bounds__(1024)
k_fuse(const int* __restrict__ mask, const float* __restrict__ c_out,
       const float* __restrict__ gate_w, const float* __restrict__ gate_b,
       float* __restrict__ out)
{
    const int b = blockIdx.x, tid = threadIdx.x;
    const int lane = tid & 31, wid = tid >> 5;

    __shared__ float red[256];
    __shared__ float sal[256];          // alpha [h][k]
    __shared__ float eahs[Hn * Dn];     // 16 KB e_att_heads for this b
    __shared__ float gred[32][5];
    __shared__ float shw[4];

    // ---- softmax over k within each h (4 groups of 64 threads) ----
    float s = 0.f;
    if (tid < 256) {
        const int hh = tid >> 6, kk = tid & 63;
        #pragma unroll
        for (int nt = 0; nt < NET; ++nt)
            s += g_upart[nt * (Bn*Hn*Kn) + ((b * Hn + hh) << 6) + kk];
        if (mask[b * Kn + kk] == 0) s = __int_as_float(0xff800000);
        red[tid] = s;
    }
    __syncthreads();
    #pragma unroll
    for (int o = 32; o; o >>= 1) {
        if (tid < 256 && (tid & 63) < o) red[tid] = fmaxf(red[tid], red[tid + o]);
        __syncthreads();
    }
    float ex = 0.f;
    if (tid < 256) {
        ex = __expf(s - red[(tid >> 6) << 6]);
    }
    __syncthreads();
    if (tid < 256) red[tid] = ex;
    __syncthreads();
    #pragma unroll
    for (int o = 32; o; o >>= 1) {
        if (tid < 256 && (tid & 63) < o) red[tid] += red[tid + o];
        __syncthreads();
    }
    if (tid < 256) {
        float al = ex / red[(tid >> 6) << 6];
        sal[tid] = al;
        out[ALPHA_OFF + b * (Hn*Kn) + tid] = al;
    }
    __syncthreads();

    // ---- e_att_heads into smem (d = tid), from fp16 E ----
    const int d = tid;
    float a0 = 0.f, a1 = 0.f, a2 = 0.f, a3 = 0.f;
    const __half* ep = g_Ef + (size_t)b * Kn * Dn + d;
    #pragma unroll 8
    for (int k = 0; k < Kn; ++k) {
        float ev = __half2float(ep[k * Dn]);
        a0 = fmaf(sal[k      ], ev, a0);
        a1 = fmaf(sal[64  + k], ev, a1);
        a2 = fmaf(sal[128 + k], ev, a2);
        a3 = fmaf(sal[192 + k], ev, a3);
    }
    eahs[         d] = a0;
    eahs[  Dn   + d] = a1;
    eahs[2*Dn   + d] = a2;
    eahs[3*Dn   + d] = a3;

    // ---- gate: pv over single d per thread; warp + cross-warp reduce ----
    const float cval = c_out[b * Dn + d];
    float pv[5];
    {
        float gwc = gate_w[d], gwe = gate_w[Dn + d];
        pv[0] = cval * gwc;
        pv[1] = a0 * gwe; pv[2] = a1 * gwe; pv[3] = a2 * gwe; pv[4] = a3 * gwe;
    }
    #pragma unroll
    for (int i = 0; i < 5; ++i) {
        float x = pv[i];
        #pragma unroll
        for (int o = 16; o; o >>= 1) x += __shfl_xor_sync(0xffffffffu, x, o);
        if (!lane) gred[wid][i] = x;
    }
    __syncthreads();
    if (wid == 0) {
        #pragma unroll
        for (int i = 0; i < 5; ++i) {
            float x = gred[lane][i];
            #pragma unroll
            for (int o = 16; o; o >>= 1) x += __shfl_xor_sync(0xffffffffu, x, o);
            if (!lane) gred[0][i] = x;
        }
        if (!lane) {
            float gb = gate_b[0];
            float g0 = gred[0][0] + gred[0][1] + gb, g1 = gred[0][0] + gred[0][2] + gb;
            float g2 = gred[0][0] + gred[0][3] + gb, g3 = gred[0][0] + gred[0][4] + gb;
            float mx = fmaxf(fmaxf(g0, g1), fmaxf(g2, g3));
            float e0 = __expf(g0 - mx), e1 = __expf(g1 - mx);
            float e2 = __expf(g2 - mx), e3 = __expf(g3 - mx);
            float inv = 1.f / (e0 + e1 + e2 + e3);
            shw[0] = e0*inv; shw[1] = e1*inv; shw[2] = e2*inv; shw[3] = e3*inv;
            out[HW_OFF + b*Hn + 0] = shw[0]; out[HW_OFF + b*Hn + 1] = shw[1];
            out[HW_OFF + b*Hn + 2] = shw[2]; out[HW_OFF + b*Hn + 3] = shw[3];
        }
    }
    __syncthreads();

    // ---- feature vector (fp16) ----
    float ea = shw[0]*a0 + shw[1]*a1 + shw[2]*a2 + shw[3]*a3;
    const size_t base = (size_t)b * KD;
    g_feath[base +        d] = __float2half_rn(cval);
    g_feath[base +   Dn + d] = __float2half_rn(ea);
    g_feath[base + 2*Dn + d] = __float2half_rn(fabsf(cval - ea));
    g_feath[base + 3*Dn + d] = __float2half_rn(cval * ea);
}

// -------- K7: hid_part = feat @ w1.T via HMMA fp16 (split-k=8) --------
__global__ void __launch_bounds__(NTHREADS, 2)
k_mlp1() {
    extern __shared__ char smem[];
    const uint32_t sb = smem_u32(smem);
    const int tid   = threadIdx.x;
    const int wid   = tid >> 5;
    const int lane  = tid & 31;
    const int warpM = wid >> 1;
    const int warpN = wid & 1;

    const int oBase   = blockIdx.x * TCN;
    const int rowBase = blockIdx.y * TCM;
    const int z       = blockIdx.z;
    const int kBase   = z * KSPAN;

    const __half* Ap = g_feath + (size_t)rowBase * KD + kBase;
    const __half* Bp = g_w1h   + (size_t)oBase * KD + kBase;

    int arow[4], ac16[4]; uint32_t aso[4];
    #pragma unroll
    for (int i = 0; i < 4; ++i) {
        int seg = tid + i * NTHREADS;
        arow[i] = seg >> 3; ac16[i] = seg & 7;
        aso[i] = SWZ128((uint32_t)(arow[i] * 128 + ac16[i] * 16));
    }

    float acc[2][8][4];
    #pragma unroll
    for (int mt = 0; mt < 2; ++mt)
        #pragma unroll
        for (int nt = 0; nt < 8; ++nt)
            #pragma unroll
            for (int j = 0; j < 4; ++j) acc[mt][nt][j] = 0.f;

    const uint32_t aRowB = (uint32_t)((warpM * 32 + (lane & 15)) * 128);
    const uint32_t bRowB = (uint32_t)((warpN * 64 + (lane & 15)) * 128);
    const uint32_t colSel = (uint32_t)((lane >> 4) * 16);

    #pragma unroll
    for (int pc = 0; pc < 2; ++pc) {
        const uint32_t st = sb + pc * STAGE_BYTES;
        const int dB = pc * KC;
        #pragma unroll
        for (int i = 0; i < 4; ++i) {
            cp16(st + OFF_A + aso[i], Ap + (size_t)arow[i] * KD + dB + ac16[i] * 8);
            cp16(st + OFF_B + aso[i], Bp + (size_t)arow[i] * KD + dB + ac16[i] * 8);
        }
        CP_COMMIT();
    }

    int stage = 0;
    for (int c = 0; c < NCHUNK_M; ++c) {
        if (c + 2 < NCHUNK_M) { CP_WAIT(1); } else { CP_WAIT(0); }
        __syncthreads();

        if (c + 2 < NCHUNK_M) {
            int ns = stage + 2; if (ns >= NSTAGE) ns -= NSTAGE;
            const uint32_t stn = sb + ns * STAGE_BYTES;
            const int dB = (c + 2) * KC;
            #pragma unroll
            for (int i = 0; i < 4; ++i) {
                cp16(stn + OFF_A + aso[i], Ap + (size_t)arow[i] * KD + dB + ac16[i] * 8);
                cp16(stn + OFF_B + aso[i], Bp + (size_t)arow[i] * KD + dB + ac16[i] * 8);
            }
            CP_COMMIT();
        }

        const uint32_t st = sb + stage * STAGE_BYTES;
        #pragma unroll
        for (int ks = 0; ks < KC / 16; ++ks) {
            const uint32_t kcol = ks * 32 + colSel;
            uint32_t af[2][4];
            #pragma unroll
            for (int mt = 0; mt < 2; ++mt) {
                uint32_t off = SWZ128(aRowB + (uint32_t)(mt * 16 * 128) + kcol);
                LDSM_X4(af[mt][0], af[mt][1], af[mt][2], af[mt][3], st + OFF_A + off);
            }
            uint32_t bf[8][2];
            #pragma unroll
            for (int p = 0; p < 4; ++p) {
                uint32_t off = SWZ128(bRowB + (uint32_t)(p * 16 * 128) + kcol);
                uint32_t r0, r1, r2, r3;
                LDSM_X4(r0, r1, r2, r3, st + OFF_B + off);
                bf[2*p][0] = r0; bf[2*p][1] = r2;
                bf[2*p+1][0] = r1; bf[2*p+1][1] = r3;
            }
            #pragma unroll
            for (int mt = 0; mt < 2; ++mt)
                #pragma unroll
                for (int nt = 0; nt < 8; ++nt)
                    MMA_F16(acc[mt][nt], af[mt], bf[nt]);
        }
        if (++stage == NSTAGE) stage = 0;
    }

    float* slab = g_hidpart + (size_t)z * (Bn * Dn);
    const int gRow = lane >> 2;
    const int gCol = (lane & 3) * 2;
    #pragma unroll
    for (int mt = 0; mt < 2; ++mt)
        #pragma unroll
        for (int h2 = 0; h2 < 2; ++h2) {
            int row = rowBase + warpM * 32 + mt * 16 + h2 * 8 + gRow;
            #pragma unroll
            for (int nt = 0; nt < 8; ++nt) {
                int col = oBase + warpN * 64 + nt * 8 + gCol;
                float2 val = make_float2(acc[mt][nt][h2*2], acc[mt][nt][h2*2+1]);
                *(float2*)&slab[(size_t)row * Dn + col] = val;
            }
        }
}

// -------- K8: relu(sum hid_parts + b1) @ w2.T + b2 -> logits --------
__global__ void k_logits(const float* __restrict__ b1, const float* __restrict__ w2,
                         const float* __restrict__ b2, float* __restrict__ out) {
    const int b = blockIdx.x, tid = threadIdx.x;
    float a0 = 0.f, a1 = 0.f, a2 = 0.f;
    for (int d = tid; d < Dn; d += 128) {
        float hp = b1[d];
        #pragma unroll
        for (int zz = 0; zz < SPLITK; ++zz)
            hp += g_hidpart[(size_t)zz * (Bn*Dn) + b*Dn + d];
        hp = fmaxf(hp, 0.f);
        a0 = fmaf(hp, w2[        d], a0);
        a1 = fmaf(hp, w2[  Dn + d], a1);
        a2 = fmaf(hp, w2[2*Dn + d], a2);
    }
    __shared__ float red[128];
    __shared__ float vals[3];
    float pv[3] = {a0, a1, a2};
    for (int i = 0; i < 3; ++i) {
        red[tid] = pv[i]; __syncthreads();
        #pragma unroll
        for (int o = 64; o; o >>= 1) { if (tid < o) red[tid] += red[tid+o]; __syncthreads(); }
        if (!tid) vals[i] = red[0];
        __syncthreads();
    }
    if (!tid) {
        out[b*NLn + 0] = vals[0] + b2[0];
        out[b*NLn + 1] = vals[1] + b2[1];
        out[b*NLn + 2] = vals[2] + b2[2];
    }
}

extern "C" void kernel_launch(void* const* d_in, const int* in_sizes, int n_in,
                              void* d_out, int out_size) {
    const float* c_out  = (const float*)d_in[0];
    const float* e_emb  = (const float*)d_in[1];
    const int*   emask  = (const int*)  d_in[2];
    const float* W_c    = (const float*)d_in[3];
    const float* W_e    = (const float*)d_in[4];
    const float* v      = (const float*)d_in[5];
    const float* gate_w = (const float*)d_in[6];
    const float* gate_b = (const float*)d_in[7];
    const float* w1     = (const float*)d_in[8];
    const float* b1     = (const float*)d_in[9];
    const float* w2     = (const float*)d_in[10];
    const float* b2     = (const float*)d_in[11];
    float* out = (float*)d_out;

    cudaFuncSetAttribute(k_attn_mma, cudaFuncAttributeMaxDynamicSharedMemorySize, SMEM_TOTAL);
    cudaFuncSetAttribute(k_mlp1, cudaFuncAttributeMaxDynamicSharedMemorySize, SMEM_TOTAL);

    k_prep<<<NBLK_E + NBLK_W + NBLK_S + NBLK_W1, 256>>>(e_emb, W_e, W_c, w1);
    k_attn_mma<<<dim3(NET, (Bn*Kn)/TCM, Hn), NTHREADS, SMEM_TOTAL>>>(c_out, v);
    k_fuse<<<Bn, 1024>>>(emask, c_out, gate_w, gate_b, out);
    k_mlp1<<<dim3(Dn/TCN, Bn/TCM, SPLITK), NTHREADS, SMEM_TOTAL>>>();
    k_logits<<<Bn, 128>>>(b1, w2, b2, out);
}